// round 11
// baseline (speedup 1.0000x reference)
#include <cuda_runtime.h>
#include <cuda_bf16.h>
#include <cstdint>

#define BB 2
#define NN 2048
#define CC 256
#define HH 8
#define HD 32
#define M_TOT (BB*NN)
#define QK_SCALE 0.17677669529663687f
#define LOG2E 1.4426950408889634f

typedef unsigned long long u64;

// ---------------- scratch (static device memory) -----------------------------
__device__ float g_q[(size_t)BB*HH*NN*HD];   // [bh][n][32] scaled by QK_SCALE
__device__ float g_k[(size_t)BB*HH*NN*HD];
__device__ float g_v[(size_t)BB*HH*NN*HD];
__device__ float g_o[(size_t)M_TOT*CC];
// attention packed operands
__device__ uint4 g_qt[(size_t)16*NN*11];   // [bh][n][88] = [qhi(36)|qlo(36)|0(16)] *LOG2E
__device__ uint4 g_ktp[(size_t)16*NN*11];  // [bh][n][88] = [khi(36)|khi(36)|0(16)]
__device__ uint4 g_vtp[(size_t)16*NN*5];   // [bh][n][40] = [v(32)|0(8)]
// projection-GEMM packed operands (3-term split, 768 bf16 = 96 uint4 per row)
__device__ uint4 g_fs[(size_t)M_TOT*96];   // feature rows: [hi|lo|hi]
__device__ uint4 g_os[(size_t)M_TOT*96];   // attention-out rows: [hi|lo|hi] (written by attn)
__device__ uint4 g_ws[(size_t)768*96];     // fused Wq|Wk|Wv cols: [hi|hi|lo]
__device__ uint4 g_wos[(size_t)256*96];    // Wo cols: [hi|hi|lo]

// ---------------- helpers -----------------------------------------------------
__device__ __forceinline__ uint32_t smem_u32(const void* p) {
    uint32_t a;
    asm("{ .reg .u64 t; cvta.to.shared.u64 t, %1; cvt.u32.u64 %0, t; }" : "=r"(a) : "l"(p));
    return a;
}
#define LDSM_X4(r, a) \
    asm volatile("ldmatrix.sync.aligned.m8n8.x4.shared.b16 {%0,%1,%2,%3}, [%4];" \
        : "=r"((r)[0]), "=r"((r)[1]), "=r"((r)[2]), "=r"((r)[3]) : "r"(a))
#define LDSM_X2(r, a) \
    asm volatile("ldmatrix.sync.aligned.m8n8.x2.shared.b16 {%0,%1}, [%2];" \
        : "=r"((r)[0]), "=r"((r)[1]) : "r"(a))
#define LDSM_X4T(r, a) \
    asm volatile("ldmatrix.sync.aligned.m8n8.x4.trans.shared.b16 {%0,%1,%2,%3}, [%4];" \
        : "=r"((r)[0]), "=r"((r)[1]), "=r"((r)[2]), "=r"((r)[3]) : "r"(a))
#define MMA16816(d, a, b0, b1) \
    asm volatile("mma.sync.aligned.m16n8k16.row.col.f32.bf16.bf16.f32 " \
        "{%0,%1,%2,%3}, {%4,%5,%6,%7}, {%8,%9}, {%0,%1,%2,%3};" \
        : "+f"((d)[0]), "+f"((d)[1]), "+f"((d)[2]), "+f"((d)[3]) \
        : "r"((a)[0]), "r"((a)[1]), "r"((a)[2]), "r"((a)[3]), "r"(b0), "r"(b1))
#define CP_ASYNC16(dst_u32, src) \
    asm volatile("cp.async.cg.shared.global [%0], [%1], 16;" :: "r"(dst_u32), "l"(src))
#define CP_COMMIT() asm volatile("cp.async.commit_group;" ::: "memory")
#define CP_WAIT(n)  asm volatile("cp.async.wait_group %0;" :: "n"(n) : "memory")

__device__ __forceinline__ void bf16_split(float v, unsigned short& hi, unsigned short& lo) {
    __nv_bfloat16 h = __float2bfloat16(v);
    __nv_bfloat16 l = __float2bfloat16(v - __bfloat162float(h));
    hi = *(unsigned short*)&h;
    lo = *(unsigned short*)&l;
}
__device__ __forceinline__ unsigned short bf16_hi(float v) {
    __nv_bfloat16 h = __float2bfloat16(v);
    return *(unsigned short*)&h;
}
__device__ __forceinline__ unsigned short bf16_lo(float v) {
    __nv_bfloat16 h = __float2bfloat16(v);
    __nv_bfloat16 l = __float2bfloat16(v - __bfloat162float(h));
    return *(unsigned short*)&l;
}

// =============================================================================
// pack_inputs: feature rows -> g_fs [hi|lo|hi]  (t < 131072)
//              weight cols  -> g_ws/g_wos [hi|hi|lo]  (t >= 131072)
// =============================================================================
__global__ void __launch_bounds__(256)
pack_inputs(const float* __restrict__ feat,
            const float* __restrict__ Wq, const float* __restrict__ Wk,
            const float* __restrict__ Wv, const float* __restrict__ Wo) {
    int t = blockIdx.x * 256 + threadIdx.x;
    if (t < 131072) {
        int row = t >> 5, cg = t & 31;
        const float* src = feat + (size_t)row*CC + cg*8;
        float4 f0 = *(const float4*)src;
        float4 f1 = *(const float4*)(src + 4);
        float v[8] = {f0.x,f0.y,f0.z,f0.w,f1.x,f1.y,f1.z,f1.w};
        unsigned short hi[8], lo[8];
        #pragma unroll
        for (int u = 0; u < 8; u++) bf16_split(v[u], hi[u], lo[u]);
        uint4 wh, wl;
        wh.x = (uint32_t)hi[0] | ((uint32_t)hi[1] << 16);
        wh.y = (uint32_t)hi[2] | ((uint32_t)hi[3] << 16);
        wh.z = (uint32_t)hi[4] | ((uint32_t)hi[5] << 16);
        wh.w = (uint32_t)hi[6] | ((uint32_t)hi[7] << 16);
        wl.x = (uint32_t)lo[0] | ((uint32_t)lo[1] << 16);
        wl.y = (uint32_t)lo[2] | ((uint32_t)lo[3] << 16);
        wl.z = (uint32_t)lo[4] | ((uint32_t)lo[5] << 16);
        wl.w = (uint32_t)lo[6] | ((uint32_t)lo[7] << 16);
        uint4* dst = g_fs + (size_t)row*96;
        dst[cg]      = wh;
        dst[32 + cg] = wl;
        dst[64 + cg] = wh;
    } else {
        int t2 = t - 131072;   // < 32768
        int row = t2 >> 5, cg = t2 & 31;
        int z = row >> 8, cc = row & 255;
        const float* W = (z == 0) ? Wq : (z == 1) ? Wk : (z == 2) ? Wv : Wo;
        unsigned short hi[8], lo[8];
        #pragma unroll
        for (int u = 0; u < 8; u++)
            bf16_split(W[(size_t)(cg*8 + u)*CC + cc], hi[u], lo[u]);
        uint4 wh, wl;
        wh.x = (uint32_t)hi[0] | ((uint32_t)hi[1] << 16);
        wh.y = (uint32_t)hi[2] | ((uint32_t)hi[3] << 16);
        wh.z = (uint32_t)hi[4] | ((uint32_t)hi[5] << 16);
        wh.w = (uint32_t)hi[6] | ((uint32_t)hi[7] << 16);
        wl.x = (uint32_t)lo[0] | ((uint32_t)lo[1] << 16);
        wl.y = (uint32_t)lo[2] | ((uint32_t)lo[3] << 16);
        wl.z = (uint32_t)lo[4] | ((uint32_t)lo[5] << 16);
        wl.w = (uint32_t)lo[6] | ((uint32_t)lo[7] << 16);
        uint4* dst = (z < 3) ? (g_ws + (size_t)row*96) : (g_wos + (size_t)(row - 768)*96);
        dst[cg]      = wh;
        dst[32 + cg] = wh;
        dst[64 + cg] = wl;
    }
}

// =============================================================================
// mma_mainloop: C[128 x 64] = A[128 x 768] * B[64 x 768]^T — round-9 passing
// =============================================================================
__device__ __forceinline__ void mma_mainloop(const uint4* __restrict__ Ap,
                                             const uint4* __restrict__ Bp,
                                             float oc[8][4]) {
    __shared__ __align__(16) unsigned short sA[2][128*40];
    __shared__ __align__(16) unsigned short sB[2][64*40];

    const int tid  = threadIdx.x;
    const int lane = tid & 31;
    const int wid  = tid >> 5;
    const int bx = blockIdx.x, by = blockIdx.y;

    #pragma unroll
    for (int i = 0; i < 8; i++)
        #pragma unroll
        for (int j = 0; j < 4; j++) oc[i][j] = 0.f;

    {
        uint32_t ad = smem_u32(&sA[0][0]);
        uint32_t bd = smem_u32(&sB[0][0]);
        for (int i = tid; i < 512; i += 256) {
            int r = i >> 2, j = i & 3;
            CP_ASYNC16(ad + r*80 + j*16, Ap + (size_t)(bx*128 + r)*96 + j);
        }
        {
            int r = tid >> 2, j = tid & 3;
            CP_ASYNC16(bd + r*80 + j*16, Bp + (size_t)(by*64 + r)*96 + j);
        }
        CP_COMMIT();
    }

    for (int t = 0; t < 24; t++) {
        if (t < 23) {
            int nb = (t + 1) & 1;
            uint32_t ad = smem_u32(&sA[nb][0]);
            uint32_t bd = smem_u32(&sB[nb][0]);
            for (int i = tid; i < 512; i += 256) {
                int r = i >> 2, j = i & 3;
                CP_ASYNC16(ad + r*80 + j*16, Ap + (size_t)(bx*128 + r)*96 + (t+1)*4 + j);
            }
            {
                int r = tid >> 2, j = tid & 3;
                CP_ASYNC16(bd + r*80 + j*16, Bp + (size_t)(by*64 + r)*96 + (t+1)*4 + j);
            }
            CP_COMMIT();
            CP_WAIT(1);
        } else {
            CP_WAIT(0);
        }
        __syncthreads();

        const int buf = t & 1;
        uint32_t qa[2][4];
        uint32_t abase = smem_u32(&sA[buf][0]) + (wid*16 + (lane & 15))*80 + (lane >> 4)*16;
        LDSM_X4(qa[0], abase);
        LDSM_X4(qa[1], abase + 32);
        uint32_t bbase = smem_u32(&sB[buf][0]) + (lane & 7)*80 + ((lane >> 3) & 3)*16;
        #pragma unroll
        for (int nt = 0; nt < 8; nt++) {
            uint32_t kb[4];
            LDSM_X4(kb, bbase + nt*640);
            MMA16816(oc[nt], qa[0], kb[0], kb[1]);
            MMA16816(oc[nt], qa[1], kb[2], kb[3]);
        }
        __syncthreads();
    }
}

// =============================================================================
// gemm_qkv_mma: grid (32, 12) — round-9 passing
// =============================================================================
__global__ void __launch_bounds__(256, 2)
gemm_qkv_mma(const float* __restrict__ bq, const float* __restrict__ bk,
             const float* __restrict__ bv) {
    float oc[8][4];
    mma_mainloop(g_fs, g_ws, oc);

    const int lane = threadIdx.x & 31;
    const int wid  = threadIdx.x >> 5;
    const int g  = lane >> 2;
    const int tq = lane & 3;
    const int r0 = blockIdx.x*128 + wid*16 + g;

    #pragma unroll
    for (int nt = 0; nt < 8; nt++) {
        int Cg = blockIdx.y*64 + nt*8 + 2*tq;
        int z = Cg >> 8, cc = Cg & 255;
        int h = cc >> 5, d = cc & 31;
        const float* bias = (z == 0) ? bq : (z == 1) ? bk : bv;
        float bb0 = bias[cc], bb1 = bias[cc + 1];
        float scale = (z == 0) ? QK_SCALE : 1.f;
        float* dbuf = (z == 0) ? g_q : (z == 1) ? g_k : g_v;
        #pragma unroll
        for (int half = 0; half < 2; half++) {
            int r = r0 + half*8;
            int b = r >> 11, n = r & (NN - 1);
            size_t idx = ((((size_t)b*HH + h)*NN + n))*HD + d;
            *(float2*)(dbuf + idx) = make_float2(
                (oc[nt][half*2 + 0] + bb0) * scale,
                (oc[nt][half*2 + 1] + bb1) * scale);
        }
    }
}

// =============================================================================
// gemm_o_mma: grid (32, 4) — round-9 passing
// =============================================================================
__global__ void __launch_bounds__(256, 2)
gemm_o_mma(const float* __restrict__ bo) {
    float oc[8][4];
    mma_mainloop(g_os, g_wos, oc);

    const int lane = threadIdx.x & 31;
    const int wid  = threadIdx.x >> 5;
    const int g  = lane >> 2;
    const int tq = lane & 3;
    const int r0 = blockIdx.x*128 + wid*16 + g;

    #pragma unroll
    for (int nt = 0; nt < 8; nt++) {
        int Cg = blockIdx.y*64 + nt*8 + 2*tq;
        float bb0 = bo[Cg], bb1 = bo[Cg + 1];
        #pragma unroll
        for (int half = 0; half < 2; half++) {
            int r = r0 + half*8;
            *(float2*)(g_o + (size_t)r*CC + Cg) = make_float2(
                oc[nt][half*2 + 0] + bb0, oc[nt][half*2 + 1] + bb1);
        }
    }
}

// =============================================================================
// conv_pack: one thread per output uint4 chunk. 27 chunks per (bh,n) row:
//   c 0..10  -> Q chunk  (cols 8c..8c+7 of [qhi(36)|qlo(36)|0(16)], *LOG2E)
//   c 11..21 -> K chunk  ([khi(36)|khi(36)|0(16)])
//   c 22..26 -> V chunk  ([v(32)|0(8)])
// id space: 16*2048*27 = 884736 threads (3456 blocks x 256).
// =============================================================================
__global__ void __launch_bounds__(256)
conv_pack(const float* __restrict__ pts) {
    int id = blockIdx.x * 256 + threadIdx.x;
    int t = id / 27;
    int c = id - t*27;
    int bh = t >> 11, n = t & (NN-1);
    int b = bh >> 3;
    int m = b*NN + n;

    unsigned short e[8];

    if (c < 22) {
        const bool isQ = (c < 11);
        int j = isQ ? c : c - 11;
        if (j >= 9) {   // chunks 9,10 are all-zero padding
            uint4 z = make_uint4(0,0,0,0);
            if (isQ) g_qt[(size_t)t*11 + j] = z;
            else     g_ktp[(size_t)t*11 + j] = z;
            return;
        }
        float px = pts[m*3+0], py = pts[m*3+1], pz = pts[m*3+2];
        const float* src = isQ ? (g_q + (size_t)t*HD) : (g_k + (size_t)t*HD);
        #pragma unroll
        for (int u = 0; u < 8; u++) {
            int col = j*8 + u;
            int i = (col < 36) ? col : col - 36;   // source element index (0..35)
            float val;
            if (i < 32)      val = src[i];
            else if (isQ) {
                val = (i == 32) ? 2.f*px : (i == 33) ? 2.f*py : (i == 34) ? 2.f*pz : 1.f;
            } else {
                val = (i == 32) ? px : (i == 33) ? py : (i == 34) ? pz
                      : -(px*px + py*py + pz*pz);
            }
            if (isQ) {
                val *= LOG2E;
                e[u] = (col < 36) ? bf16_hi(val) : bf16_lo(val);
            } else {
                e[u] = bf16_hi(val);
            }
        }
        uint4 w;
        w.x = (uint32_t)e[0] | ((uint32_t)e[1] << 16);
        w.y = (uint32_t)e[2] | ((uint32_t)e[3] << 16);
        w.z = (uint32_t)e[4] | ((uint32_t)e[5] << 16);
        w.w = (uint32_t)e[6] | ((uint32_t)e[7] << 16);
        if (isQ) g_qt[(size_t)t*11 + j] = w;
        else     g_ktp[(size_t)t*11 + j] = w;
    } else {
        int j = c - 22;
        if (j == 4) {
            g_vtp[(size_t)t*5 + 4] = make_uint4(0,0,0,0);
            return;
        }
        const float* src = g_v + (size_t)t*HD + j*8;
        float4 f0 = *(const float4*)src;
        float4 f1 = *(const float4*)(src + 4);
        float v[8] = {f0.x,f0.y,f0.z,f0.w,f1.x,f1.y,f1.z,f1.w};
        #pragma unroll
        for (int u = 0; u < 8; u++) e[u] = bf16_hi(v[u]);
        uint4 w;
        w.x = (uint32_t)e[0] | ((uint32_t)e[1] << 16);
        w.y = (uint32_t)e[2] | ((uint32_t)e[3] << 16);
        w.z = (uint32_t)e[4] | ((uint32_t)e[5] << 16);
        w.w = (uint32_t)e[6] | ((uint32_t)e[7] << 16);
        g_vtp[(size_t)t*5 + j] = w;
    }
}

// =============================================================================
// attn_mma: flash attention, m16n8k16 bf16, 2-term split.
// Epilogue writes the [hi|lo|hi] split rows of g_os directly (no g_att).
// =============================================================================
#define KROW 88
#define VROW 40

__global__ void __launch_bounds__(256, 2)
attn_mma() {
    __shared__ __align__(16) unsigned short sK[2][64*KROW];
    __shared__ __align__(16) unsigned short sV[2][64*VROW];

    const int tid  = threadIdx.x;
    const int lane = tid & 31;
    const int wid  = tid >> 5;
    const int bh = blockIdx.y;
    const int qt = blockIdx.x;
    const int b = bh >> 3, h = bh & 7;

    {
        const uint4* src = g_qt + ((size_t)bh*NN + qt*128) * 11;
        uint4* dst = (uint4*)&sK[0][0];
        for (int i = tid; i < 1408; i += 256) dst[i] = src[i];
    }
    __syncthreads();

    uint32_t qa[5][4];
    {
        uint32_t qbase = smem_u32(&sK[0][0]) + (wid*16 + (lane & 15))*176 + (lane >> 4)*16;
        #pragma unroll
        for (int c = 0; c < 5; c++) LDSM_X4(qa[c], qbase + c*32);
    }
    __syncthreads();

    float oc[4][4];
    #pragma unroll
    for (int i = 0; i < 4; i++)
        #pragma unroll
        for (int j = 0; j < 4; j++) oc[i][j] = 0.f;
    float ls0 = 0.f, ls1 = 0.f;

    const uint4* kg_src = g_ktp + (size_t)bh*NN*11;
    const uint4* vg_src = g_vtp + (size_t)bh*NN*5;

    {
        uint32_t kd = smem_u32(&sK[0][0]);
        uint32_t vd = smem_u32(&sV[0][0]);
        for (int i = tid; i < 704; i += 256) CP_ASYNC16(kd + i*16, kg_src + i);
        for (int i = tid; i < 320; i += 256) CP_ASYNC16(vd + i*16, vg_src + i);
        CP_COMMIT();
    }

    for (int t = 0; t < 32; t++) {
        if (t < 31) {
            int nb = (t + 1) & 1;
            uint32_t kd = smem_u32(&sK[nb][0]);
            uint32_t vd = smem_u32(&sV[nb][0]);
            const uint4* ks = kg_src + (size_t)(t+1)*64*11;
            const uint4* vs = vg_src + (size_t)(t+1)*64*5;
            for (int i = tid; i < 704; i += 256) CP_ASYNC16(kd + i*16, ks + i);
            for (int i = tid; i < 320; i += 256) CP_ASYNC16(vd + i*16, vs + i);
            CP_COMMIT();
            CP_WAIT(1);
        } else {
            CP_WAIT(0);
        }
        __syncthreads();

        const int buf = t & 1;
        uint32_t kbase = smem_u32(&sK[buf][0]);
        uint32_t vbase = smem_u32(&sV[buf][0]);

        float sc[8][4];
        #pragma unroll
        for (int kg = 0; kg < 8; kg++) {
            #pragma unroll
            for (int j = 0; j < 4; j++) sc[kg][j] = 0.f;
            uint32_t kb[10];
            uint32_t krow = kbase + (kg*8 + (lane & 7))*176;
            uint32_t ka = krow + ((lane >> 3) & 3)*16;
            LDSM_X4(&kb[0], ka);
            LDSM_X4(&kb[4], ka + 64);
            LDSM_X2(&kb[8], krow + 128 + ((lane >> 3) & 1)*16);
            #pragma unroll
            for (int c = 0; c < 5; c++)
                MMA16816(sc[kg], qa[c], kb[2*c], kb[2*c+1]);
        }

        uint32_t pa[4][4];
        #pragma unroll
        for (int pc = 0; pc < 4; pc++) {
            float e[8];
            #pragma unroll
            for (int half = 0; half < 2; half++) {
                const float* s = sc[2*pc + half];
                #pragma unroll
                for (int j = 0; j < 4; j++)
                    asm("ex2.approx.f32 %0, %1;" : "=f"(e[half*4 + j]) : "f"(s[j]));
            }
            ls0 += (e[0] + e[1]) + (e[4] + e[5]);
            ls1 += (e[2] + e[3]) + (e[6] + e[7]);
            asm("cvt.rn.bf16x2.f32 %0, %1, %2;" : "=r"(pa[pc][0]) : "f"(e[1]), "f"(e[0]));
            asm("cvt.rn.bf16x2.f32 %0, %1, %2;" : "=r"(pa[pc][1]) : "f"(e[3]), "f"(e[2]));
            asm("cvt.rn.bf16x2.f32 %0, %1, %2;" : "=r"(pa[pc][2]) : "f"(e[5]), "f"(e[4]));
            asm("cvt.rn.bf16x2.f32 %0, %1, %2;" : "=r"(pa[pc][3]) : "f"(e[7]), "f"(e[6]));
        }

        #pragma unroll
        for (int hp = 0; hp < 2; hp++) {
            #pragma unroll
            for (int pc = 0; pc < 4; pc++) {
                uint32_t vb[4];
                uint32_t va = vbase + (pc*16 + (lane & 15))*80 + hp*32 + (lane >> 4)*16;
                LDSM_X4T(vb, va);
                MMA16816(oc[2*hp],     pa[pc], vb[0], vb[1]);
                MMA16816(oc[2*hp + 1], pa[pc], vb[2], vb[3]);
            }
        }
        __syncthreads();
    }

    ls0 += __shfl_xor_sync(0xFFFFFFFFu, ls0, 1);
    ls0 += __shfl_xor_sync(0xFFFFFFFFu, ls0, 2);
    ls1 += __shfl_xor_sync(0xFFFFFFFFu, ls1, 1);
    ls1 += __shfl_xor_sync(0xFFFFFFFFu, ls1, 2);
    float inv0 = 1.f / ls0;
    float inv1 = 1.f / ls1;

    const int g  = lane >> 2;
    const int tq = lane & 3;
    const int row0 = qt*128 + wid*16 + g;
    uint32_t* orow0 = (uint32_t*)g_os + (size_t)(b*NN + row0)*384;
    uint32_t* orow1 = (uint32_t*)g_os + (size_t)(b*NN + row0 + 8)*384;
    #pragma unroll
    for (int n = 0; n < 4; n++) {
        int idx = h*16 + n*4 + tq;          // uint32 index within 256-col section
        unsigned short h0, l0, h1, l1;
        bf16_split(oc[n][0]*inv0, h0, l0);
        bf16_split(oc[n][1]*inv0, h1, l1);
        uint32_t uh = (uint32_t)h0 | ((uint32_t)h1 << 16);
        uint32_t ul = (uint32_t)l0 | ((uint32_t)l1 << 16);
        orow0[idx]       = uh;
        orow0[idx + 128] = ul;
        orow0[idx + 256] = uh;
        bf16_split(oc[n][2]*inv1, h0, l0);
        bf16_split(oc[n][3]*inv1, h1, l1);
        uh = (uint32_t)h0 | ((uint32_t)h1 << 16);
        ul = (uint32_t)l0 | ((uint32_t)l1 << 16);
        orow1[idx]       = uh;
        orow1[idx + 128] = ul;
        orow1[idx + 256] = uh;
    }
}

// =============================================================================
// Residual + LayerNorm
// =============================================================================
__global__ void __launch_bounds__(256)
ln_kernel(const float* __restrict__ feat,
          const float* __restrict__ ln_g, const float* __restrict__ ln_b,
          float* __restrict__ out) {
    const int m = blockIdx.x;
    const int c = threadIdx.x;
    float f = feat[(size_t)m*CC + c] + g_o[(size_t)m*CC + c];

    __shared__ float red[256];
    red[c] = f;
    __syncthreads();
    #pragma unroll
    for (int s = 128; s > 0; s >>= 1) {
        if (c < s) red[c] += red[c + s];
        __syncthreads();
    }
    float mu = red[0] * (1.f/256.f);
    __syncthreads();
    float d = f - mu;
    red[c] = d * d;
    __syncthreads();
    #pragma unroll
    for (int s = 128; s > 0; s >>= 1) {
        if (c < s) red[c] += red[c + s];
        __syncthreads();
    }
    float var = red[0] * (1.f/256.f);
    out[(size_t)m*CC + c] = d * rsqrtf(var + 1e-5f) * ln_g[c] + ln_b[c];
}

// =============================================================================
extern "C" void kernel_launch(void* const* d_in, const int* in_sizes, int n_in,
                              void* d_out, int out_size) {
    const float* feature = (const float*)d_in[0];
    const float* points  = (const float*)d_in[1];
    const float* Wq = (const float*)d_in[2];
    const float* bq = (const float*)d_in[3];
    const float* Wk = (const float*)d_in[4];
    const float* bk = (const float*)d_in[5];
    const float* Wv = (const float*)d_in[6];
    const float* bv = (const float*)d_in[7];
    const float* Wo = (const float*)d_in[8];
    const float* bo = (const float*)d_in[9];
    const float* ln_g = (const float*)d_in[10];
    const float* ln_b = (const float*)d_in[11];
    float* out = (float*)d_out;

    pack_inputs<<<640, 256>>>(feature, Wq, Wk, Wv, Wo);

    dim3 gq(32, 12);
    gemm_qkv_mma<<<gq, 256>>>(bq, bk, bv);

    conv_pack<<<3456, 256>>>(points);

    dim3 ga(16, 16);
    attn_mma<<<ga, 256>>>();

    dim3 go(32, 4);
    gemm_o_mma<<<go, 256>>>(bo);

    ln_kernel<<<M_TOT, 256>>>(feature, ln_g, ln_b, out);
}

// round 12
// speedup vs baseline: 1.1629x; 1.1629x over previous
#include <cuda_runtime.h>
#include <cuda_bf16.h>
#include <cstdint>

#define BB 2
#define NN 2048
#define CC 256
#define HH 8
#define HD 32
#define M_TOT (BB*NN)
#define QK_SCALE 0.17677669529663687f
#define LOG2E 1.4426950408889634f

typedef unsigned long long u64;

// ---------------- scratch (static device memory) -----------------------------
__device__ float g_q[(size_t)BB*HH*NN*HD];   // [bh][n][32] scaled by QK_SCALE
__device__ float g_k[(size_t)BB*HH*NN*HD];
__device__ float g_v[(size_t)BB*HH*NN*HD];
__device__ float g_o[(size_t)M_TOT*CC];
// attention packed operands (1-term bf16: 48 bf16 = 6 uint4 per Q/K row)
__device__ uint4 g_qt[(size_t)16*NN*6];    // [bh][n][48] = [qhi(36)|0(12)] *LOG2E
__device__ uint4 g_ktp[(size_t)16*NN*6];   // [bh][n][48] = [khi(36)|0(12)]
__device__ uint4 g_vtp[(size_t)16*NN*5];   // [bh][n][40] = [v(32)|0(8)]
// projection-GEMM packed operands (3-term split, 768 bf16 = 96 uint4 per row)
__device__ uint4 g_fs[(size_t)M_TOT*96];   // feature rows: [hi|lo|hi]
__device__ uint4 g_os[(size_t)M_TOT*96];   // attention-out rows: [hi|lo|hi] (written by attn)
__device__ uint4 g_ws[(size_t)768*96];     // fused Wq|Wk|Wv cols: [hi|hi|lo]
__device__ uint4 g_wos[(size_t)256*96];    // Wo cols: [hi|hi|lo]

// ---------------- helpers -----------------------------------------------------
__device__ __forceinline__ uint32_t smem_u32(const void* p) {
    uint32_t a;
    asm("{ .reg .u64 t; cvta.to.shared.u64 t, %1; cvt.u32.u64 %0, t; }" : "=r"(a) : "l"(p));
    return a;
}
#define LDSM_X4(r, a) \
    asm volatile("ldmatrix.sync.aligned.m8n8.x4.shared.b16 {%0,%1,%2,%3}, [%4];" \
        : "=r"((r)[0]), "=r"((r)[1]), "=r"((r)[2]), "=r"((r)[3]) : "r"(a))
#define LDSM_X2(r, a) \
    asm volatile("ldmatrix.sync.aligned.m8n8.x2.shared.b16 {%0,%1}, [%2];" \
        : "=r"((r)[0]), "=r"((r)[1]) : "r"(a))
#define LDSM_X4T(r, a) \
    asm volatile("ldmatrix.sync.aligned.m8n8.x4.trans.shared.b16 {%0,%1,%2,%3}, [%4];" \
        : "=r"((r)[0]), "=r"((r)[1]), "=r"((r)[2]), "=r"((r)[3]) : "r"(a))
#define MMA16816(d, a, b0, b1) \
    asm volatile("mma.sync.aligned.m16n8k16.row.col.f32.bf16.bf16.f32 " \
        "{%0,%1,%2,%3}, {%4,%5,%6,%7}, {%8,%9}, {%0,%1,%2,%3};" \
        : "+f"((d)[0]), "+f"((d)[1]), "+f"((d)[2]), "+f"((d)[3]) \
        : "r"((a)[0]), "r"((a)[1]), "r"((a)[2]), "r"((a)[3]), "r"(b0), "r"(b1))
#define CP_ASYNC16(dst_u32, src) \
    asm volatile("cp.async.cg.shared.global [%0], [%1], 16;" :: "r"(dst_u32), "l"(src))
#define CP_COMMIT() asm volatile("cp.async.commit_group;" ::: "memory")
#define CP_WAIT(n)  asm volatile("cp.async.wait_group %0;" :: "n"(n) : "memory")

__device__ __forceinline__ void bf16_split(float v, unsigned short& hi, unsigned short& lo) {
    __nv_bfloat16 h = __float2bfloat16(v);
    __nv_bfloat16 l = __float2bfloat16(v - __bfloat162float(h));
    hi = *(unsigned short*)&h;
    lo = *(unsigned short*)&l;
}
__device__ __forceinline__ unsigned short bf16_hi(float v) {
    __nv_bfloat16 h = __float2bfloat16(v);
    return *(unsigned short*)&h;
}

// =============================================================================
// pack_inputs: feature rows -> g_fs [hi|lo|hi]  (t < 131072)
//              weight cols  -> g_ws/g_wos [hi|hi|lo]  (t >= 131072)
// =============================================================================
__global__ void __launch_bounds__(256)
pack_inputs(const float* __restrict__ feat,
            const float* __restrict__ Wq, const float* __restrict__ Wk,
            const float* __restrict__ Wv, const float* __restrict__ Wo) {
    int t = blockIdx.x * 256 + threadIdx.x;
    if (t < 131072) {
        int row = t >> 5, cg = t & 31;
        const float* src = feat + (size_t)row*CC + cg*8;
        float4 f0 = *(const float4*)src;
        float4 f1 = *(const float4*)(src + 4);
        float v[8] = {f0.x,f0.y,f0.z,f0.w,f1.x,f1.y,f1.z,f1.w};
        unsigned short hi[8], lo[8];
        #pragma unroll
        for (int u = 0; u < 8; u++) bf16_split(v[u], hi[u], lo[u]);
        uint4 wh, wl;
        wh.x = (uint32_t)hi[0] | ((uint32_t)hi[1] << 16);
        wh.y = (uint32_t)hi[2] | ((uint32_t)hi[3] << 16);
        wh.z = (uint32_t)hi[4] | ((uint32_t)hi[5] << 16);
        wh.w = (uint32_t)hi[6] | ((uint32_t)hi[7] << 16);
        wl.x = (uint32_t)lo[0] | ((uint32_t)lo[1] << 16);
        wl.y = (uint32_t)lo[2] | ((uint32_t)lo[3] << 16);
        wl.z = (uint32_t)lo[4] | ((uint32_t)lo[5] << 16);
        wl.w = (uint32_t)lo[6] | ((uint32_t)lo[7] << 16);
        uint4* dst = g_fs + (size_t)row*96;
        dst[cg]      = wh;
        dst[32 + cg] = wl;
        dst[64 + cg] = wh;
    } else {
        int t2 = t - 131072;   // < 32768
        int row = t2 >> 5, cg = t2 & 31;
        int z = row >> 8, cc = row & 255;
        const float* W = (z == 0) ? Wq : (z == 1) ? Wk : (z == 2) ? Wv : Wo;
        unsigned short hi[8], lo[8];
        #pragma unroll
        for (int u = 0; u < 8; u++)
            bf16_split(W[(size_t)(cg*8 + u)*CC + cc], hi[u], lo[u]);
        uint4 wh, wl;
        wh.x = (uint32_t)hi[0] | ((uint32_t)hi[1] << 16);
        wh.y = (uint32_t)hi[2] | ((uint32_t)hi[3] << 16);
        wh.z = (uint32_t)hi[4] | ((uint32_t)hi[5] << 16);
        wh.w = (uint32_t)hi[6] | ((uint32_t)hi[7] << 16);
        wl.x = (uint32_t)lo[0] | ((uint32_t)lo[1] << 16);
        wl.y = (uint32_t)lo[2] | ((uint32_t)lo[3] << 16);
        wl.z = (uint32_t)lo[4] | ((uint32_t)lo[5] << 16);
        wl.w = (uint32_t)lo[6] | ((uint32_t)lo[7] << 16);
        uint4* dst = (z < 3) ? (g_ws + (size_t)row*96) : (g_wos + (size_t)(row - 768)*96);
        dst[cg]      = wh;
        dst[32 + cg] = wh;
        dst[64 + cg] = wl;
    }
}

// =============================================================================
// mma_mainloop: C[128 x 64] = A[128 x 768] * B[64 x 768]^T — unchanged
// =============================================================================
__device__ __forceinline__ void mma_mainloop(const uint4* __restrict__ Ap,
                                             const uint4* __restrict__ Bp,
                                             float oc[8][4]) {
    __shared__ __align__(16) unsigned short sA[2][128*40];
    __shared__ __align__(16) unsigned short sB[2][64*40];

    const int tid  = threadIdx.x;
    const int lane = tid & 31;
    const int wid  = tid >> 5;
    const int bx = blockIdx.x, by = blockIdx.y;

    #pragma unroll
    for (int i = 0; i < 8; i++)
        #pragma unroll
        for (int j = 0; j < 4; j++) oc[i][j] = 0.f;

    {
        uint32_t ad = smem_u32(&sA[0][0]);
        uint32_t bd = smem_u32(&sB[0][0]);
        for (int i = tid; i < 512; i += 256) {
            int r = i >> 2, j = i & 3;
            CP_ASYNC16(ad + r*80 + j*16, Ap + (size_t)(bx*128 + r)*96 + j);
        }
        {
            int r = tid >> 2, j = tid & 3;
            CP_ASYNC16(bd + r*80 + j*16, Bp + (size_t)(by*64 + r)*96 + j);
        }
        CP_COMMIT();
    }

    for (int t = 0; t < 24; t++) {
        if (t < 23) {
            int nb = (t + 1) & 1;
            uint32_t ad = smem_u32(&sA[nb][0]);
            uint32_t bd = smem_u32(&sB[nb][0]);
            for (int i = tid; i < 512; i += 256) {
                int r = i >> 2, j = i & 3;
                CP_ASYNC16(ad + r*80 + j*16, Ap + (size_t)(bx*128 + r)*96 + (t+1)*4 + j);
            }
            {
                int r = tid >> 2, j = tid & 3;
                CP_ASYNC16(bd + r*80 + j*16, Bp + (size_t)(by*64 + r)*96 + (t+1)*4 + j);
            }
            CP_COMMIT();
            CP_WAIT(1);
        } else {
            CP_WAIT(0);
        }
        __syncthreads();

        const int buf = t & 1;
        uint32_t qa[2][4];
        uint32_t abase = smem_u32(&sA[buf][0]) + (wid*16 + (lane & 15))*80 + (lane >> 4)*16;
        LDSM_X4(qa[0], abase);
        LDSM_X4(qa[1], abase + 32);
        uint32_t bbase = smem_u32(&sB[buf][0]) + (lane & 7)*80 + ((lane >> 3) & 3)*16;
        #pragma unroll
        for (int nt = 0; nt < 8; nt++) {
            uint32_t kb[4];
            LDSM_X4(kb, bbase + nt*640);
            MMA16816(oc[nt], qa[0], kb[0], kb[1]);
            MMA16816(oc[nt], qa[1], kb[2], kb[3]);
        }
        __syncthreads();
    }
}

// =============================================================================
// gemm_qkv_mma: grid (32, 12) — unchanged
// =============================================================================
__global__ void __launch_bounds__(256, 2)
gemm_qkv_mma(const float* __restrict__ bq, const float* __restrict__ bk,
             const float* __restrict__ bv) {
    float oc[8][4];
    mma_mainloop(g_fs, g_ws, oc);

    const int lane = threadIdx.x & 31;
    const int wid  = threadIdx.x >> 5;
    const int g  = lane >> 2;
    const int tq = lane & 3;
    const int r0 = blockIdx.x*128 + wid*16 + g;

    #pragma unroll
    for (int nt = 0; nt < 8; nt++) {
        int Cg = blockIdx.y*64 + nt*8 + 2*tq;
        int z = Cg >> 8, cc = Cg & 255;
        int h = cc >> 5, d = cc & 31;
        const float* bias = (z == 0) ? bq : (z == 1) ? bk : bv;
        float bb0 = bias[cc], bb1 = bias[cc + 1];
        float scale = (z == 0) ? QK_SCALE : 1.f;
        float* dbuf = (z == 0) ? g_q : (z == 1) ? g_k : g_v;
        #pragma unroll
        for (int half = 0; half < 2; half++) {
            int r = r0 + half*8;
            int b = r >> 11, n = r & (NN - 1);
            size_t idx = ((((size_t)b*HH + h)*NN + n))*HD + d;
            *(float2*)(dbuf + idx) = make_float2(
                (oc[nt][half*2 + 0] + bb0) * scale,
                (oc[nt][half*2 + 1] + bb1) * scale);
        }
    }
}

// =============================================================================
// gemm_o_mma: grid (32, 4) — unchanged
// =============================================================================
__global__ void __launch_bounds__(256, 2)
gemm_o_mma(const float* __restrict__ bo) {
    float oc[8][4];
    mma_mainloop(g_os, g_wos, oc);

    const int lane = threadIdx.x & 31;
    const int wid  = threadIdx.x >> 5;
    const int g  = lane >> 2;
    const int tq = lane & 3;
    const int r0 = blockIdx.x*128 + wid*16 + g;

    #pragma unroll
    for (int nt = 0; nt < 8; nt++) {
        int Cg = blockIdx.y*64 + nt*8 + 2*tq;
        float bb0 = bo[Cg], bb1 = bo[Cg + 1];
        #pragma unroll
        for (int half = 0; half < 2; half++) {
            int r = r0 + half*8;
            *(float2*)(g_o + (size_t)r*CC + Cg) = make_float2(
                oc[nt][half*2 + 0] + bb0, oc[nt][half*2 + 1] + bb1);
        }
    }
}

// =============================================================================
// conv_pack: one thread per output uint4 chunk. 17 chunks per (bh,n) row:
//   c 0..5   -> Q chunk  ([qhi(36)|0(12)], *LOG2E)
//   c 6..11  -> K chunk  ([khi(36)|0(12)])
//   c 12..16 -> V chunk  ([v(32)|0(8)])
// id space: 16*2048*17 = 557056 threads (2176 blocks x 256).
// =============================================================================
__global__ void __launch_bounds__(256)
conv_pack(const float* __restrict__ pts) {
    int id = blockIdx.x * 256 + threadIdx.x;
    int t = id / 17;
    int c = id - t*17;
    int bh = t >> 11, n = t & (NN-1);
    int b = bh >> 3;
    int m = b*NN + n;

    unsigned short e[8];

    if (c < 12) {
        const bool isQ = (c < 6);
        int j = isQ ? c : c - 6;
        if (j == 5) {   // cols 40..47 all zero
            if (isQ) g_qt[(size_t)t*6 + 5] = make_uint4(0,0,0,0);
            else     g_ktp[(size_t)t*6 + 5] = make_uint4(0,0,0,0);
            return;
        }
        const float* src = isQ ? (g_q + (size_t)t*HD) : (g_k + (size_t)t*HD);
        if (j < 4) {
            const float* s8 = src + j*8;
            float4 f0 = *(const float4*)s8;
            float4 f1 = *(const float4*)(s8 + 4);
            float v[8] = {f0.x,f0.y,f0.z,f0.w,f1.x,f1.y,f1.z,f1.w};
            #pragma unroll
            for (int u = 0; u < 8; u++)
                e[u] = bf16_hi(isQ ? v[u]*LOG2E : v[u]);
        } else {        // j == 4: cols 32..35 aug, 36..39 zero
            float px = pts[m*3+0], py = pts[m*3+1], pz = pts[m*3+2];
            float a0, a1, a2, a3;
            if (isQ) {
                a0 = 2.f*px*LOG2E; a1 = 2.f*py*LOG2E; a2 = 2.f*pz*LOG2E; a3 = LOG2E;
            } else {
                a0 = px; a1 = py; a2 = pz; a3 = -(px*px + py*py + pz*pz);
            }
            e[0] = bf16_hi(a0); e[1] = bf16_hi(a1);
            e[2] = bf16_hi(a2); e[3] = bf16_hi(a3);
            e[4] = e[5] = e[6] = e[7] = 0;
        }
        uint4 w;
        w.x = (uint32_t)e[0] | ((uint32_t)e[1] << 16);
        w.y = (uint32_t)e[2] | ((uint32_t)e[3] << 16);
        w.z = (uint32_t)e[4] | ((uint32_t)e[5] << 16);
        w.w = (uint32_t)e[6] | ((uint32_t)e[7] << 16);
        if (isQ) g_qt[(size_t)t*6 + j] = w;
        else     g_ktp[(size_t)t*6 + j] = w;
    } else {
        int j = c - 12;
        if (j == 4) {
            g_vtp[(size_t)t*5 + 4] = make_uint4(0,0,0,0);
            return;
        }
        const float* src = g_v + (size_t)t*HD + j*8;
        float4 f0 = *(const float4*)src;
        float4 f1 = *(const float4*)(src + 4);
        float v[8] = {f0.x,f0.y,f0.z,f0.w,f1.x,f1.y,f1.z,f1.w};
        #pragma unroll
        for (int u = 0; u < 8; u++) e[u] = bf16_hi(v[u]);
        uint4 w;
        w.x = (uint32_t)e[0] | ((uint32_t)e[1] << 16);
        w.y = (uint32_t)e[2] | ((uint32_t)e[3] << 16);
        w.z = (uint32_t)e[4] | ((uint32_t)e[5] << 16);
        w.w = (uint32_t)e[6] | ((uint32_t)e[7] << 16);
        g_vtp[(size_t)t*5 + j] = w;
    }
}

// =============================================================================
// attn_mma: flash attention, m16n8k16 bf16, 1-term logits (contract 48).
// smem K/Q row stride 112B (conflict-free: r*112 mod 128 covers all 8 phases).
// Epilogue writes [hi|lo|hi] split rows of g_os directly.
// =============================================================================
#define KROWB 112   // smem row stride bytes for K/Q (48 bf16 data + pad)
#define VROW 40     // bf16 per V row (80 B)

__global__ void __launch_bounds__(256, 2)
attn_mma() {
    __shared__ __align__(16) unsigned char sK[2][64*KROWB];  // 2 x 7168 B
    __shared__ __align__(16) unsigned short sV[2][64*VROW];  // 2 x 5120 B

    const int tid  = threadIdx.x;
    const int lane = tid & 31;
    const int wid  = tid >> 5;
    const int bh = blockIdx.y;
    const int qt = blockIdx.x;
    const int b = bh >> 3, h = bh & 7;

    // ---- stage Q (128 rows x 96B data, stride 112B across sK[0]+sK[1])
    {
        const uint4* src = g_qt + ((size_t)bh*NN + qt*128) * 6;
        for (int i = tid; i < 768; i += 256) {
            int r = i / 6, j = i - r*6;
            *(uint4*)(&sK[0][0] + r*KROWB + j*16) = src[i];
        }
    }
    __syncthreads();

    // ---- load Q fragments: 3 k16-chunks
    uint32_t qa[3][4];
    {
        uint32_t qbase = smem_u32(&sK[0][0]) + (wid*16 + (lane & 15))*KROWB + (lane >> 4)*16;
        #pragma unroll
        for (int c = 0; c < 3; c++) LDSM_X4(qa[c], qbase + c*32);
    }
    __syncthreads();

    float oc[4][4];
    #pragma unroll
    for (int i = 0; i < 4; i++)
        #pragma unroll
        for (int j = 0; j < 4; j++) oc[i][j] = 0.f;
    float ls0 = 0.f, ls1 = 0.f;

    const uint4* kg_src = g_ktp + (size_t)bh*NN*6;
    const uint4* vg_src = g_vtp + (size_t)bh*NN*5;

    // prefetch tile 0: K = 384 uint4, V = 320 uint4
    {
        uint32_t kd = smem_u32(&sK[0][0]);
        uint32_t vd = smem_u32(&sV[0][0]);
        for (int i = tid; i < 384; i += 256) {
            int r = i / 6, j = i - r*6;
            CP_ASYNC16(kd + r*KROWB + j*16, kg_src + i);
        }
        for (int i = tid; i < 320; i += 256) CP_ASYNC16(vd + i*16, vg_src + i);
        CP_COMMIT();
    }

    for (int t = 0; t < 32; t++) {
        if (t < 31) {
            int nb = (t + 1) & 1;
            uint32_t kd = smem_u32(&sK[nb][0]);
            uint32_t vd = smem_u32(&sV[nb][0]);
            const uint4* ks = kg_src + (size_t)(t+1)*64*6;
            const uint4* vs = vg_src + (size_t)(t+1)*64*5;
            for (int i = tid; i < 384; i += 256) {
                int r = i / 6, j = i - r*6;
                CP_ASYNC16(kd + r*KROWB + j*16, ks + i);
            }
            for (int i = tid; i < 320; i += 256) CP_ASYNC16(vd + i*16, vs + i);
            CP_COMMIT();
            CP_WAIT(1);
        } else {
            CP_WAIT(0);
        }
        __syncthreads();

        const int buf = t & 1;
        uint32_t kbase = smem_u32(&sK[buf][0]);
        uint32_t vbase = smem_u32(&sV[buf][0]);

        // ---- S = Q~ K~^T  (8 n-tiles of 8 keys, contract 48)
        float sc[8][4];
        #pragma unroll
        for (int kg = 0; kg < 8; kg++) {
            #pragma unroll
            for (int j = 0; j < 4; j++) sc[kg][j] = 0.f;
            uint32_t kb[6];
            uint32_t krow = kbase + (kg*8 + (lane & 7))*KROWB;
            LDSM_X4(&kb[0], krow + ((lane >> 3) & 3)*16);
            LDSM_X2(&kb[4], krow + 64 + ((lane >> 3) & 1)*16);
            #pragma unroll
            for (int c = 0; c < 3; c++)
                MMA16816(sc[kg], qa[c], kb[2*c], kb[2*c+1]);
        }

        // ---- softmax (exp2; row-sum accumulate) -> P A-fragments
        uint32_t pa[4][4];
        #pragma unroll
        for (int pc = 0; pc < 4; pc++) {
            float e[8];
            #pragma unroll
            for (int half = 0; half < 2; half++) {
                const float* s = sc[2*pc + half];
                #pragma unroll
                for (int j = 0; j < 4; j++)
                    asm("ex2.approx.f32 %0, %1;" : "=f"(e[half*4 + j]) : "f"(s[j]));
            }
            ls0 += (e[0] + e[1]) + (e[4] + e[5]);
            ls1 += (e[2] + e[3]) + (e[6] + e[7]);
            asm("cvt.rn.bf16x2.f32 %0, %1, %2;" : "=r"(pa[pc][0]) : "f"(e[1]), "f"(e[0]));
            asm("cvt.rn.bf16x2.f32 %0, %1, %2;" : "=r"(pa[pc][1]) : "f"(e[3]), "f"(e[2]));
            asm("cvt.rn.bf16x2.f32 %0, %1, %2;" : "=r"(pa[pc][2]) : "f"(e[5]), "f"(e[4]));
            asm("cvt.rn.bf16x2.f32 %0, %1, %2;" : "=r"(pa[pc][3]) : "f"(e[7]), "f"(e[6]));
        }

        // ---- O += P V
        #pragma unroll
        for (int hp = 0; hp < 2; hp++) {
            #pragma unroll
            for (int pc = 0; pc < 4; pc++) {
                uint32_t vb[4];
                uint32_t va = vbase + (pc*16 + (lane & 15))*80 + hp*32 + (lane >> 4)*16;
                LDSM_X4T(vb, va);
                MMA16816(oc[2*hp],     pa[pc], vb[0], vb[1]);
                MMA16816(oc[2*hp + 1], pa[pc], vb[2], vb[3]);
            }
        }
        __syncthreads();
    }

    ls0 += __shfl_xor_sync(0xFFFFFFFFu, ls0, 1);
    ls0 += __shfl_xor_sync(0xFFFFFFFFu, ls0, 2);
    ls1 += __shfl_xor_sync(0xFFFFFFFFu, ls1, 1);
    ls1 += __shfl_xor_sync(0xFFFFFFFFu, ls1, 2);
    float inv0 = 1.f / ls0;
    float inv1 = 1.f / ls1;

    const int g  = lane >> 2;
    const int tq = lane & 3;
    const int row0 = qt*128 + wid*16 + g;
    uint32_t* orow0 = (uint32_t*)g_os + (size_t)(b*NN + row0)*384;
    uint32_t* orow1 = (uint32_t*)g_os + (size_t)(b*NN + row0 + 8)*384;
    #pragma unroll
    for (int n = 0; n < 4; n++) {
        int idx = h*16 + n*4 + tq;
        unsigned short h0, l0, h1, l1;
        bf16_split(oc[n][0]*inv0, h0, l0);
        bf16_split(oc[n][1]*inv0, h1, l1);
        uint32_t uh = (uint32_t)h0 | ((uint32_t)h1 << 16);
        uint32_t ul = (uint32_t)l0 | ((uint32_t)l1 << 16);
        orow0[idx]       = uh;
        orow0[idx + 128] = ul;
        orow0[idx + 256] = uh;
        bf16_split(oc[n][2]*inv1, h0, l0);
        bf16_split(oc[n][3]*inv1, h1, l1);
        uh = (uint32_t)h0 | ((uint32_t)h1 << 16);
        ul = (uint32_t)l0 | ((uint32_t)l1 << 16);
        orow1[idx]       = uh;
        orow1[idx + 128] = ul;
        orow1[idx + 256] = uh;
    }
}

// =============================================================================
// Residual + LayerNorm
// =============================================================================
__global__ void __launch_bounds__(256)
ln_kernel(const float* __restrict__ feat,
          const float* __restrict__ ln_g, const float* __restrict__ ln_b,
          float* __restrict__ out) {
    const int m = blockIdx.x;
    const int c = threadIdx.x;
    float f = feat[(size_t)m*CC + c] + g_o[(size_t)m*CC + c];

    __shared__ float red[256];
    red[c] = f;
    __syncthreads();
    #pragma unroll
    for (int s = 128; s > 0; s >>= 1) {
        if (c < s) red[c] += red[c + s];
        __syncthreads();
    }
    float mu = red[0] * (1.f/256.f);
    __syncthreads();
    float d = f - mu;
    red[c] = d * d;
    __syncthreads();
    #pragma unroll
    for (int s = 128; s > 0; s >>= 1) {
        if (c < s) red[c] += red[c + s];
        __syncthreads();
    }
    float var = red[0] * (1.f/256.f);
    out[(size_t)m*CC + c] = d * rsqrtf(var + 1e-5f) * ln_g[c] + ln_b[c];
}

// =============================================================================
extern "C" void kernel_launch(void* const* d_in, const int* in_sizes, int n_in,
                              void* d_out, int out_size) {
    const float* feature = (const float*)d_in[0];
    const float* points  = (const float*)d_in[1];
    const float* Wq = (const float*)d_in[2];
    const float* bq = (const float*)d_in[3];
    const float* Wk = (const float*)d_in[4];
    const float* bk = (const float*)d_in[5];
    const float* Wv = (const float*)d_in[6];
    const float* bv = (const float*)d_in[7];
    const float* Wo = (const float*)d_in[8];
    const float* bo = (const float*)d_in[9];
    const float* ln_g = (const float*)d_in[10];
    const float* ln_b = (const float*)d_in[11];
    float* out = (float*)d_out;

    pack_inputs<<<640, 256>>>(feature, Wq, Wk, Wv, Wo);

    dim3 gq(32, 12);
    gemm_qkv_mma<<<gq, 256>>>(bq, bk, bv);

    conv_pack<<<2176, 256>>>(points);

    dim3 ga(16, 16);
    attn_mma<<<ga, 256>>>();

    dim3 go(32, 4);
    gemm_o_mma<<<go, 256>>>(bo);

    ln_kernel<<<M_TOT, 256>>>(feature, ln_g, ln_b, out);
}

// round 13
// speedup vs baseline: 1.2783x; 1.0992x over previous
#include <cuda_runtime.h>
#include <cuda_bf16.h>
#include <cstdint>

#define BB 2
#define NN 2048
#define CC 256
#define HH 8
#define HD 32
#define M_TOT (BB*NN)
#define QK_SCALE 0.17677669529663687f
#define LOG2E 1.4426950408889634f
#define QKL (QK_SCALE * LOG2E)

typedef unsigned long long u64;

// ---------------- scratch (static device memory) -----------------------------
__device__ float g_o[(size_t)M_TOT*CC];
// attention packed operands (1-term bf16: 48 bf16 = 6 uint4 per Q/K row)
__device__ uint4 g_qt[(size_t)16*NN*6];    // [bh][n][48] = [qhi(36)|0(12)] *QK_SCALE*LOG2E
__device__ uint4 g_ktp[(size_t)16*NN*6];   // [bh][n][48] = [khi(36)|0(12)]
__device__ uint4 g_vtp[(size_t)16*NN*5];   // [bh][n][40] = [v(32)|0(8)]
// projection-GEMM packed operands (3-term split, 768 bf16 = 96 uint4 per row)
__device__ uint4 g_fs[(size_t)M_TOT*96];   // feature rows: [hi|lo|hi]
__device__ uint4 g_os[(size_t)M_TOT*96];   // attention-out rows: [hi|lo|hi] (written by attn)
__device__ uint4 g_ws[(size_t)768*96];     // fused Wq|Wk|Wv cols: [hi|hi|lo]
__device__ uint4 g_wos[(size_t)256*96];    // Wo cols: [hi|hi|lo]

// ---------------- helpers -----------------------------------------------------
__device__ __forceinline__ uint32_t smem_u32(const void* p) {
    uint32_t a;
    asm("{ .reg .u64 t; cvta.to.shared.u64 t, %1; cvt.u32.u64 %0, t; }" : "=r"(a) : "l"(p));
    return a;
}
#define LDSM_X4(r, a) \
    asm volatile("ldmatrix.sync.aligned.m8n8.x4.shared.b16 {%0,%1,%2,%3}, [%4];" \
        : "=r"((r)[0]), "=r"((r)[1]), "=r"((r)[2]), "=r"((r)[3]) : "r"(a))
#define LDSM_X2(r, a) \
    asm volatile("ldmatrix.sync.aligned.m8n8.x2.shared.b16 {%0,%1}, [%2];" \
        : "=r"((r)[0]), "=r"((r)[1]) : "r"(a))
#define LDSM_X4T(r, a) \
    asm volatile("ldmatrix.sync.aligned.m8n8.x4.trans.shared.b16 {%0,%1,%2,%3}, [%4];" \
        : "=r"((r)[0]), "=r"((r)[1]), "=r"((r)[2]), "=r"((r)[3]) : "r"(a))
#define MMA16816(d, a, b0, b1) \
    asm volatile("mma.sync.aligned.m16n8k16.row.col.f32.bf16.bf16.f32 " \
        "{%0,%1,%2,%3}, {%4,%5,%6,%7}, {%8,%9}, {%0,%1,%2,%3};" \
        : "+f"((d)[0]), "+f"((d)[1]), "+f"((d)[2]), "+f"((d)[3]) \
        : "r"((a)[0]), "r"((a)[1]), "r"((a)[2]), "r"((a)[3]), "r"(b0), "r"(b1))
#define CP_ASYNC16(dst_u32, src) \
    asm volatile("cp.async.cg.shared.global [%0], [%1], 16;" :: "r"(dst_u32), "l"(src))
#define CP_COMMIT() asm volatile("cp.async.commit_group;" ::: "memory")
#define CP_WAIT(n)  asm volatile("cp.async.wait_group %0;" :: "n"(n) : "memory")
#define CVT_BF16X2(d, hi, lo) \
    asm("cvt.rn.bf16x2.f32 %0, %1, %2;" : "=r"(d) : "f"(hi), "f"(lo))

__device__ __forceinline__ void bf16_split(float v, unsigned short& hi, unsigned short& lo) {
    __nv_bfloat16 h = __float2bfloat16(v);
    __nv_bfloat16 l = __float2bfloat16(v - __bfloat162float(h));
    hi = *(unsigned short*)&h;
    lo = *(unsigned short*)&l;
}
__device__ __forceinline__ unsigned short bf16_hi(float v) {
    __nv_bfloat16 h = __float2bfloat16(v);
    return *(unsigned short*)&h;
}

// =============================================================================
// pack_inputs: t < 131072          feature rows -> g_fs [hi|lo|hi]
//              131072 <= t < 163840 weight cols -> g_ws/g_wos [hi|hi|lo]
//              163840 <= t < 196608 aug chunks (from points) -> g_qt/g_ktp/g_vtp
// =============================================================================
__global__ void __launch_bounds__(256)
pack_inputs(const float* __restrict__ feat,
            const float* __restrict__ Wq, const float* __restrict__ Wk,
            const float* __restrict__ Wv, const float* __restrict__ Wo,
            const float* __restrict__ pts) {
    int t = blockIdx.x * 256 + threadIdx.x;
    if (t < 131072) {
        int row = t >> 5, cg = t & 31;
        const float* src = feat + (size_t)row*CC + cg*8;
        float4 f0 = *(const float4*)src;
        float4 f1 = *(const float4*)(src + 4);
        float v[8] = {f0.x,f0.y,f0.z,f0.w,f1.x,f1.y,f1.z,f1.w};
        unsigned short hi[8], lo[8];
        #pragma unroll
        for (int u = 0; u < 8; u++) bf16_split(v[u], hi[u], lo[u]);
        uint4 wh, wl;
        wh.x = (uint32_t)hi[0] | ((uint32_t)hi[1] << 16);
        wh.y = (uint32_t)hi[2] | ((uint32_t)hi[3] << 16);
        wh.z = (uint32_t)hi[4] | ((uint32_t)hi[5] << 16);
        wh.w = (uint32_t)hi[6] | ((uint32_t)hi[7] << 16);
        wl.x = (uint32_t)lo[0] | ((uint32_t)lo[1] << 16);
        wl.y = (uint32_t)lo[2] | ((uint32_t)lo[3] << 16);
        wl.z = (uint32_t)lo[4] | ((uint32_t)lo[5] << 16);
        wl.w = (uint32_t)lo[6] | ((uint32_t)lo[7] << 16);
        uint4* dst = g_fs + (size_t)row*96;
        dst[cg]      = wh;
        dst[32 + cg] = wl;
        dst[64 + cg] = wh;
    } else if (t < 163840) {
        int t2 = t - 131072;   // < 32768
        int row = t2 >> 5, cg = t2 & 31;
        int z = row >> 8, cc = row & 255;
        const float* W = (z == 0) ? Wq : (z == 1) ? Wk : (z == 2) ? Wv : Wo;
        unsigned short hi[8], lo[8];
        #pragma unroll
        for (int u = 0; u < 8; u++)
            bf16_split(W[(size_t)(cg*8 + u)*CC + cc], hi[u], lo[u]);
        uint4 wh, wl;
        wh.x = (uint32_t)hi[0] | ((uint32_t)hi[1] << 16);
        wh.y = (uint32_t)hi[2] | ((uint32_t)hi[3] << 16);
        wh.z = (uint32_t)hi[4] | ((uint32_t)hi[5] << 16);
        wh.w = (uint32_t)hi[6] | ((uint32_t)hi[7] << 16);
        wl.x = (uint32_t)lo[0] | ((uint32_t)lo[1] << 16);
        wl.y = (uint32_t)lo[2] | ((uint32_t)lo[3] << 16);
        wl.z = (uint32_t)lo[4] | ((uint32_t)lo[5] << 16);
        wl.w = (uint32_t)lo[6] | ((uint32_t)lo[7] << 16);
        uint4* dst = (z < 3) ? (g_ws + (size_t)row*96) : (g_wos + (size_t)(row - 768)*96);
        dst[cg]      = wh;
        dst[32 + cg] = wh;
        dst[64 + cg] = wl;
    } else {
        int t3 = t - 163840;   // < 32768 : one (bh, n)
        int bh = t3 >> 11, n = t3 & (NN-1);
        int b = bh >> 3;
        int m = b*NN + n;
        float px = pts[m*3+0], py = pts[m*3+1], pz = pts[m*3+2];
        float p2 = px*px + py*py + pz*pz;
        uint4 zr = make_uint4(0,0,0,0);
        uint4 wq, wk;
        wq.x = (uint32_t)bf16_hi(2.f*px*LOG2E) | ((uint32_t)bf16_hi(2.f*py*LOG2E) << 16);
        wq.y = (uint32_t)bf16_hi(2.f*pz*LOG2E) | ((uint32_t)bf16_hi(LOG2E) << 16);
        wq.z = 0; wq.w = 0;
        wk.x = (uint32_t)bf16_hi(px) | ((uint32_t)bf16_hi(py) << 16);
        wk.y = (uint32_t)bf16_hi(pz) | ((uint32_t)bf16_hi(-p2) << 16);
        wk.z = 0; wk.w = 0;
        g_qt[(size_t)t3*6 + 4]  = wq;
        g_qt[(size_t)t3*6 + 5]  = zr;
        g_ktp[(size_t)t3*6 + 4] = wk;
        g_ktp[(size_t)t3*6 + 5] = zr;
        g_vtp[(size_t)t3*5 + 4] = zr;
    }
}

// =============================================================================
// mma_mainloop: C[128 x 64] = A[128 x 768] * B[64 x 768]^T — unchanged
// =============================================================================
__device__ __forceinline__ void mma_mainloop(const uint4* __restrict__ Ap,
                                             const uint4* __restrict__ Bp,
                                             float oc[8][4]) {
    __shared__ __align__(16) unsigned short sA[2][128*40];
    __shared__ __align__(16) unsigned short sB[2][64*40];

    const int tid  = threadIdx.x;
    const int lane = tid & 31;
    const int wid  = tid >> 5;
    const int bx = blockIdx.x, by = blockIdx.y;

    #pragma unroll
    for (int i = 0; i < 8; i++)
        #pragma unroll
        for (int j = 0; j < 4; j++) oc[i][j] = 0.f;

    {
        uint32_t ad = smem_u32(&sA[0][0]);
        uint32_t bd = smem_u32(&sB[0][0]);
        for (int i = tid; i < 512; i += 256) {
            int r = i >> 2, j = i & 3;
            CP_ASYNC16(ad + r*80 + j*16, Ap + (size_t)(bx*128 + r)*96 + j);
        }
        {
            int r = tid >> 2, j = tid & 3;
            CP_ASYNC16(bd + r*80 + j*16, Bp + (size_t)(by*64 + r)*96 + j);
        }
        CP_COMMIT();
    }

    for (int t = 0; t < 24; t++) {
        if (t < 23) {
            int nb = (t + 1) & 1;
            uint32_t ad = smem_u32(&sA[nb][0]);
            uint32_t bd = smem_u32(&sB[nb][0]);
            for (int i = tid; i < 512; i += 256) {
                int r = i >> 2, j = i & 3;
                CP_ASYNC16(ad + r*80 + j*16, Ap + (size_t)(bx*128 + r)*96 + (t+1)*4 + j);
            }
            {
                int r = tid >> 2, j = tid & 3;
                CP_ASYNC16(bd + r*80 + j*16, Bp + (size_t)(by*64 + r)*96 + (t+1)*4 + j);
            }
            CP_COMMIT();
            CP_WAIT(1);
        } else {
            CP_WAIT(0);
        }
        __syncthreads();

        const int buf = t & 1;
        uint32_t qa[2][4];
        uint32_t abase = smem_u32(&sA[buf][0]) + (wid*16 + (lane & 15))*80 + (lane >> 4)*16;
        LDSM_X4(qa[0], abase);
        LDSM_X4(qa[1], abase + 32);
        uint32_t bbase = smem_u32(&sB[buf][0]) + (lane & 7)*80 + ((lane >> 3) & 3)*16;
        #pragma unroll
        for (int nt = 0; nt < 8; nt++) {
            uint32_t kb[4];
            LDSM_X4(kb, bbase + nt*640);
            MMA16816(oc[nt], qa[0], kb[0], kb[1]);
            MMA16816(oc[nt], qa[1], kb[2], kb[3]);
        }
        __syncthreads();
    }
}

// =============================================================================
// gemm_qkv_mma: grid (32, 12). Epilogue writes bf16 packs DIRECTLY into
// g_qt / g_ktp / g_vtp (same rounding as the old fp32->conv_pack path).
// =============================================================================
__global__ void __launch_bounds__(256, 2)
gemm_qkv_mma(const float* __restrict__ bq, const float* __restrict__ bk,
             const float* __restrict__ bv) {
    float oc[8][4];
    mma_mainloop(g_fs, g_ws, oc);

    const int lane = threadIdx.x & 31;
    const int wid  = threadIdx.x >> 5;
    const int g  = lane >> 2;
    const int tq = lane & 3;
    const int r0 = blockIdx.x*128 + wid*16 + g;

    #pragma unroll
    for (int nt = 0; nt < 8; nt++) {
        int Cg = blockIdx.y*64 + nt*8 + 2*tq;
        int z = Cg >> 8, cc = Cg & 255;
        int h = cc >> 5, d = cc & 31;
        const float* bias = (z == 0) ? bq : (z == 1) ? bk : bv;
        float bb0 = bias[cc], bb1 = bias[cc + 1];
        #pragma unroll
        for (int half = 0; half < 2; half++) {
            int r = r0 + half*8;
            int b = r >> 11, n = r & (NN - 1);
            size_t tt = ((size_t)b*HH + h)*NN + n;
            float v0 = oc[nt][half*2 + 0] + bb0;
            float v1 = oc[nt][half*2 + 1] + bb1;
            uint32_t packed;
            if (z == 0) {
                CVT_BF16X2(packed, v1*QKL, v0*QKL);
                ((uint32_t*)g_qt)[tt*24 + (d >> 1)] = packed;
            } else if (z == 1) {
                CVT_BF16X2(packed, v1, v0);
                ((uint32_t*)g_ktp)[tt*24 + (d >> 1)] = packed;
            } else {
                CVT_BF16X2(packed, v1, v0);
                ((uint32_t*)g_vtp)[tt*20 + (d >> 1)] = packed;
            }
        }
    }
}

// =============================================================================
// gemm_o_mma: grid (32, 4) — unchanged
// =============================================================================
__global__ void __launch_bounds__(256, 2)
gemm_o_mma(const float* __restrict__ bo) {
    float oc[8][4];
    mma_mainloop(g_os, g_wos, oc);

    const int lane = threadIdx.x & 31;
    const int wid  = threadIdx.x >> 5;
    const int g  = lane >> 2;
    const int tq = lane & 3;
    const int r0 = blockIdx.x*128 + wid*16 + g;

    #pragma unroll
    for (int nt = 0; nt < 8; nt++) {
        int Cg = blockIdx.y*64 + nt*8 + 2*tq;
        float bb0 = bo[Cg], bb1 = bo[Cg + 1];
        #pragma unroll
        for (int half = 0; half < 2; half++) {
            int r = r0 + half*8;
            *(float2*)(g_o + (size_t)r*CC + Cg) = make_float2(
                oc[nt][half*2 + 0] + bb0, oc[nt][half*2 + 1] + bb1);
        }
    }
}

// =============================================================================
// attn_mma: flash attention, m16n8k16 bf16, 1-term logits — round-12 passing
// =============================================================================
#define KROWB 112
#define VROW 40

__global__ void __launch_bounds__(256, 2)
attn_mma() {
    __shared__ __align__(16) unsigned char sK[2][64*KROWB];
    __shared__ __align__(16) unsigned short sV[2][64*VROW];

    const int tid  = threadIdx.x;
    const int lane = tid & 31;
    const int wid  = tid >> 5;
    const int bh = blockIdx.y;
    const int qt = blockIdx.x;
    const int b = bh >> 3, h = bh & 7;

    {
        const uint4* src = g_qt + ((size_t)bh*NN + qt*128) * 6;
        for (int i = tid; i < 768; i += 256) {
            int r = i / 6, j = i - r*6;
            *(uint4*)(&sK[0][0] + r*KROWB + j*16) = src[i];
        }
    }
    __syncthreads();

    uint32_t qa[3][4];
    {
        uint32_t qbase = smem_u32(&sK[0][0]) + (wid*16 + (lane & 15))*KROWB + (lane >> 4)*16;
        #pragma unroll
        for (int c = 0; c < 3; c++) LDSM_X4(qa[c], qbase + c*32);
    }
    __syncthreads();

    float oc[4][4];
    #pragma unroll
    for (int i = 0; i < 4; i++)
        #pragma unroll
        for (int j = 0; j < 4; j++) oc[i][j] = 0.f;
    float ls0 = 0.f, ls1 = 0.f;

    const uint4* kg_src = g_ktp + (size_t)bh*NN*6;
    const uint4* vg_src = g_vtp + (size_t)bh*NN*5;

    {
        uint32_t kd = smem_u32(&sK[0][0]);
        uint32_t vd = smem_u32(&sV[0][0]);
        for (int i = tid; i < 384; i += 256) {
            int r = i / 6, j = i - r*6;
            CP_ASYNC16(kd + r*KROWB + j*16, kg_src + i);
        }
        for (int i = tid; i < 320; i += 256) CP_ASYNC16(vd + i*16, vg_src + i);
        CP_COMMIT();
    }

    for (int t = 0; t < 32; t++) {
        if (t < 31) {
            int nb = (t + 1) & 1;
            uint32_t kd = smem_u32(&sK[nb][0]);
            uint32_t vd = smem_u32(&sV[nb][0]);
            const uint4* ks = kg_src + (size_t)(t+1)*64*6;
            const uint4* vs = vg_src + (size_t)(t+1)*64*5;
            for (int i = tid; i < 384; i += 256) {
                int r = i / 6, j = i - r*6;
                CP_ASYNC16(kd + r*KROWB + j*16, ks + i);
            }
            for (int i = tid; i < 320; i += 256) CP_ASYNC16(vd + i*16, vs + i);
            CP_COMMIT();
            CP_WAIT(1);
        } else {
            CP_WAIT(0);
        }
        __syncthreads();

        const int buf = t & 1;
        uint32_t kbase = smem_u32(&sK[buf][0]);
        uint32_t vbase = smem_u32(&sV[buf][0]);

        float sc[8][4];
        #pragma unroll
        for (int kg = 0; kg < 8; kg++) {
            #pragma unroll
            for (int j = 0; j < 4; j++) sc[kg][j] = 0.f;
            uint32_t kb[6];
            uint32_t krow = kbase + (kg*8 + (lane & 7))*KROWB;
            LDSM_X4(&kb[0], krow + ((lane >> 3) & 3)*16);
            LDSM_X2(&kb[4], krow + 64 + ((lane >> 3) & 1)*16);
            #pragma unroll
            for (int c = 0; c < 3; c++)
                MMA16816(sc[kg], qa[c], kb[2*c], kb[2*c+1]);
        }

        uint32_t pa[4][4];
        #pragma unroll
        for (int pc = 0; pc < 4; pc++) {
            float e[8];
            #pragma unroll
            for (int half = 0; half < 2; half++) {
                const float* s = sc[2*pc + half];
                #pragma unroll
                for (int j = 0; j < 4; j++)
                    asm("ex2.approx.f32 %0, %1;" : "=f"(e[half*4 + j]) : "f"(s[j]));
            }
            ls0 += (e[0] + e[1]) + (e[4] + e[5]);
            ls1 += (e[2] + e[3]) + (e[6] + e[7]);
            CVT_BF16X2(pa[pc][0], e[1], e[0]);
            CVT_BF16X2(pa[pc][1], e[3], e[2]);
            CVT_BF16X2(pa[pc][2], e[5], e[4]);
            CVT_BF16X2(pa[pc][3], e[7], e[6]);
        }

        #pragma unroll
        for (int hp = 0; hp < 2; hp++) {
            #pragma unroll
            for (int pc = 0; pc < 4; pc++) {
                uint32_t vb[4];
                uint32_t va = vbase + (pc*16 + (lane & 15))*80 + hp*32 + (lane >> 4)*16;
                LDSM_X4T(vb, va);
                MMA16816(oc[2*hp],     pa[pc], vb[0], vb[1]);
                MMA16816(oc[2*hp + 1], pa[pc], vb[2], vb[3]);
            }
        }
        __syncthreads();
    }

    ls0 += __shfl_xor_sync(0xFFFFFFFFu, ls0, 1);
    ls0 += __shfl_xor_sync(0xFFFFFFFFu, ls0, 2);
    ls1 += __shfl_xor_sync(0xFFFFFFFFu, ls1, 1);
    ls1 += __shfl_xor_sync(0xFFFFFFFFu, ls1, 2);
    float inv0 = 1.f / ls0;
    float inv1 = 1.f / ls1;

    const int g  = lane >> 2;
    const int tq = lane & 3;
    const int row0 = qt*128 + wid*16 + g;
    uint32_t* orow0 = (uint32_t*)g_os + (size_t)(b*NN + row0)*384;
    uint32_t* orow1 = (uint32_t*)g_os + (size_t)(b*NN + row0 + 8)*384;
    #pragma unroll
    for (int n = 0; n < 4; n++) {
        int idx = h*16 + n*4 + tq;
        unsigned short h0, l0, h1, l1;
        bf16_split(oc[n][0]*inv0, h0, l0);
        bf16_split(oc[n][1]*inv0, h1, l1);
        uint32_t uh = (uint32_t)h0 | ((uint32_t)h1 << 16);
        uint32_t ul = (uint32_t)l0 | ((uint32_t)l1 << 16);
        orow0[idx]       = uh;
        orow0[idx + 128] = ul;
        orow0[idx + 256] = uh;
        bf16_split(oc[n][2]*inv1, h0, l0);
        bf16_split(oc[n][3]*inv1, h1, l1);
        uh = (uint32_t)h0 | ((uint32_t)h1 << 16);
        ul = (uint32_t)l0 | ((uint32_t)l1 << 16);
        orow1[idx]       = uh;
        orow1[idx + 128] = ul;
        orow1[idx + 256] = uh;
    }
}

// =============================================================================
// Residual + LayerNorm — one warp per row, shuffle reductions, no smem/barriers
// =============================================================================
__global__ void __launch_bounds__(256)
ln_kernel(const float* __restrict__ feat,
          const float* __restrict__ ln_g, const float* __restrict__ ln_b,
          float* __restrict__ out) {
    const int lane = threadIdx.x & 31;
    const int wid  = threadIdx.x >> 5;
    const int m = blockIdx.x*8 + wid;

    const float4* f4 = (const float4*)(feat + (size_t)m*CC) + lane*2;
    const float4* o4 = (const float4*)(g_o + (size_t)m*CC) + lane*2;
    float4 a0 = f4[0], a1 = f4[1];
    float4 b0 = o4[0], b1 = o4[1];
    float v[8] = {a0.x+b0.x, a0.y+b0.y, a0.z+b0.z, a0.w+b0.w,
                  a1.x+b1.x, a1.y+b1.y, a1.z+b1.z, a1.w+b1.w};

    float s = 0.f, s2 = 0.f;
    #pragma unroll
    for (int u = 0; u < 8; u++) { s += v[u]; s2 += v[u]*v[u]; }
    #pragma unroll
    for (int d = 16; d > 0; d >>= 1) {
        s  += __shfl_xor_sync(0xFFFFFFFFu, s,  d);
        s2 += __shfl_xor_sync(0xFFFFFFFFu, s2, d);
    }
    float mu  = s * (1.f/256.f);
    float var = s2 * (1.f/256.f) - mu*mu;
    float r = rsqrtf(var + 1e-5f);

    const float4* g4 = (const float4*)ln_g + lane*2;
    const float4* bb4 = (const float4*)ln_b + lane*2;
    float4 g0 = g4[0], g1 = g4[1];
    float4 c0 = bb4[0], c1 = bb4[1];
    float gg[8] = {g0.x,g0.y,g0.z,g0.w,g1.x,g1.y,g1.z,g1.w};
    float cc[8] = {c0.x,c0.y,c0.z,c0.w,c1.x,c1.y,c1.z,c1.w};

    float4 o0, o1;
    o0.x = (v[0]-mu)*r*gg[0] + cc[0];
    o0.y = (v[1]-mu)*r*gg[1] + cc[1];
    o0.z = (v[2]-mu)*r*gg[2] + cc[2];
    o0.w = (v[3]-mu)*r*gg[3] + cc[3];
    o1.x = (v[4]-mu)*r*gg[4] + cc[4];
    o1.y = (v[5]-mu)*r*gg[5] + cc[5];
    o1.z = (v[6]-mu)*r*gg[6] + cc[6];
    o1.w = (v[7]-mu)*r*gg[7] + cc[7];
    float4* dst = (float4*)(out + (size_t)m*CC) + lane*2;
    dst[0] = o0;
    dst[1] = o1;
}

// =============================================================================
extern "C" void kernel_launch(void* const* d_in, const int* in_sizes, int n_in,
                              void* d_out, int out_size) {
    const float* feature = (const float*)d_in[0];
    const float* points  = (const float*)d_in[1];
    const float* Wq = (const float*)d_in[2];
    const float* bq = (const float*)d_in[3];
    const float* Wk = (const float*)d_in[4];
    const float* bk = (const float*)d_in[5];
    const float* Wv = (const float*)d_in[6];
    const float* bv = (const float*)d_in[7];
    const float* Wo = (const float*)d_in[8];
    const float* bo = (const float*)d_in[9];
    const float* ln_g = (const float*)d_in[10];
    const float* ln_b = (const float*)d_in[11];
    float* out = (float*)d_out;

    pack_inputs<<<768, 256>>>(feature, Wq, Wk, Wv, Wo, points);

    dim3 gq(32, 12);
    gemm_qkv_mma<<<gq, 256>>>(bq, bk, bv);

    dim3 ga(16, 16);
    attn_mma<<<ga, 256>>>();

    dim3 go(32, 4);
    gemm_o_mma<<<go, 256>>>(bo);

    ln_kernel<<<512, 256>>>(feature, ln_g, ln_b, out);
}

// round 15
// speedup vs baseline: 1.7346x; 1.3570x over previous
#include <cuda_runtime.h>
#include <cuda_bf16.h>
#include <cstdint>

#define BB 2
#define NN 2048
#define CC 256
#define HH 8
#define HD 32
#define M_TOT (BB*NN)
#define QK_SCALE 0.17677669529663687f
#define LOG2E 1.4426950408889634f
#define QKL (QK_SCALE * LOG2E)

typedef unsigned long long u64;

// ---------------- scratch (static device memory) -----------------------------
__device__ float g_o[(size_t)M_TOT*CC];
// attention packed operands (1-term bf16: 48 bf16 = 6 uint4 per Q/K row)
__device__ uint4 g_qt[(size_t)16*NN*6];    // [bh][n][48] = [qhi(36)|0(12)] *QK_SCALE*LOG2E
__device__ uint4 g_ktp[(size_t)16*NN*6];   // [bh][n][48] = [khi(36)|0(12)]
__device__ uint4 g_vtp[(size_t)16*NN*5];   // [bh][n][40] = [v(32)|0(8)]
// projection-GEMM operands (pure bf16, 256 bf16 = 32 uint4 per row)
__device__ uint4 g_fs[(size_t)M_TOT*32];   // feature rows bf16
__device__ uint4 g_os[(size_t)M_TOT*32];   // attention-out rows bf16 (written by attn)
__device__ uint4 g_ws[(size_t)768*32];     // fused Wq|Wk|Wv cols bf16
__device__ uint4 g_wos[(size_t)256*32];    // Wo cols bf16

// ---------------- helpers -----------------------------------------------------
__device__ __forceinline__ uint32_t smem_u32(const void* p) {
    uint32_t a;
    asm("{ .reg .u64 t; cvta.to.shared.u64 t, %1; cvt.u32.u64 %0, t; }" : "=r"(a) : "l"(p));
    return a;
}
#define LDSM_X4(r, a) \
    asm volatile("ldmatrix.sync.aligned.m8n8.x4.shared.b16 {%0,%1,%2,%3}, [%4];" \
        : "=r"((r)[0]), "=r"((r)[1]), "=r"((r)[2]), "=r"((r)[3]) : "r"(a))
#define LDSM_X2(r, a) \
    asm volatile("ldmatrix.sync.aligned.m8n8.x2.shared.b16 {%0,%1}, [%2];" \
        : "=r"((r)[0]), "=r"((r)[1]) : "r"(a))
#define LDSM_X4T(r, a) \
    asm volatile("ldmatrix.sync.aligned.m8n8.x4.trans.shared.b16 {%0,%1,%2,%3}, [%4];" \
        : "=r"((r)[0]), "=r"((r)[1]), "=r"((r)[2]), "=r"((r)[3]) : "r"(a))
#define MMA16816(d, a, b0, b1) \
    asm volatile("mma.sync.aligned.m16n8k16.row.col.f32.bf16.bf16.f32 " \
        "{%0,%1,%2,%3}, {%4,%5,%6,%7}, {%8,%9}, {%0,%1,%2,%3};" \
        : "+f"((d)[0]), "+f"((d)[1]), "+f"((d)[2]), "+f"((d)[3]) \
        : "r"((a)[0]), "r"((a)[1]), "r"((a)[2]), "r"((a)[3]), "r"(b0), "r"(b1))
#define CP_ASYNC16(dst_u32, src) \
    asm volatile("cp.async.cg.shared.global [%0], [%1], 16;" :: "r"(dst_u32), "l"(src))
#define CP_COMMIT() asm volatile("cp.async.commit_group;" ::: "memory")
#define CP_WAIT(n)  asm volatile("cp.async.wait_group %0;" :: "n"(n) : "memory")
#define CVT_BF16X2(d, hi, lo) \
    asm("cvt.rn.bf16x2.f32 %0, %1, %2;" : "=r"(d) : "f"(hi), "f"(lo))

__device__ __forceinline__ unsigned short bf16_hi(float v) {
    __nv_bfloat16 h = __float2bfloat16(v);
    return *(unsigned short*)&h;
}

// =============================================================================
// pack_inputs: t < 131072           feature rows -> g_fs (bf16)
//              131072 <= t < 163840 weight cols -> g_ws/g_wos (bf16)
//              163840 <= t < 196608 aug chunks (from points) -> g_qt/g_ktp/g_vtp
// =============================================================================
__global__ void __launch_bounds__(256)
pack_inputs(const float* __restrict__ feat,
            const float* __restrict__ Wq, const float* __restrict__ Wk,
            const float* __restrict__ Wv, const float* __restrict__ Wo,
            const float* __restrict__ pts) {
    int t = blockIdx.x * 256 + threadIdx.x;
    if (t < 131072) {
        int row = t >> 5, cg = t & 31;
        const float* src = feat + (size_t)row*CC + cg*8;
        float4 f0 = *(const float4*)src;
        float4 f1 = *(const float4*)(src + 4);
        uint4 wh;
        CVT_BF16X2(wh.x, f0.y, f0.x);
        CVT_BF16X2(wh.y, f0.w, f0.z);
        CVT_BF16X2(wh.z, f1.y, f1.x);
        CVT_BF16X2(wh.w, f1.w, f1.z);
        g_fs[(size_t)row*32 + cg] = wh;
    } else if (t < 163840) {
        int t2 = t - 131072;   // < 32768
        int row = t2 >> 5, cg = t2 & 31;
        int z = row >> 8, cc = row & 255;
        const float* W = (z == 0) ? Wq : (z == 1) ? Wk : (z == 2) ? Wv : Wo;
        float v[8];
        #pragma unroll
        for (int u = 0; u < 8; u++) v[u] = W[(size_t)(cg*8 + u)*CC + cc];
        uint4 wh;
        CVT_BF16X2(wh.x, v[1], v[0]);
        CVT_BF16X2(wh.y, v[3], v[2]);
        CVT_BF16X2(wh.z, v[5], v[4]);
        CVT_BF16X2(wh.w, v[7], v[6]);
        uint4* dst = (z < 3) ? (g_ws + (size_t)row*32) : (g_wos + (size_t)(row - 768)*32);
        dst[cg] = wh;
    } else {
        int t3 = t - 163840;   // < 32768 : one (bh, n)
        int bh = t3 >> 11, n = t3 & (NN-1);
        int b = bh >> 3;
        int m = b*NN + n;
        float px = pts[m*3+0], py = pts[m*3+1], pz = pts[m*3+2];
        float p2 = px*px + py*py + pz*pz;
        uint4 zr = make_uint4(0,0,0,0);
        uint4 wq, wk;
        wq.x = (uint32_t)bf16_hi(2.f*px*LOG2E) | ((uint32_t)bf16_hi(2.f*py*LOG2E) << 16);
        wq.y = (uint32_t)bf16_hi(2.f*pz*LOG2E) | ((uint32_t)bf16_hi(LOG2E) << 16);
        wq.z = 0; wq.w = 0;
        wk.x = (uint32_t)bf16_hi(px) | ((uint32_t)bf16_hi(py) << 16);
        wk.y = (uint32_t)bf16_hi(pz) | ((uint32_t)bf16_hi(-p2) << 16);
        wk.z = 0; wk.w = 0;
        g_qt[(size_t)t3*6 + 4]  = wq;
        g_qt[(size_t)t3*6 + 5]  = zr;
        g_ktp[(size_t)t3*6 + 4] = wk;
        g_ktp[(size_t)t3*6 + 5] = zr;
        g_vtp[(size_t)t3*5 + 4] = zr;
    }
}

// =============================================================================
// mma_mainloop: C[128 x 64] = A[128 x 256] * B[64 x 256]^T, pure bf16.
// 8 k32 iterations, double-buffered cp.async. smem row stride 40 bf16 (80B).
// =============================================================================
__device__ __forceinline__ void mma_mainloop(const uint4* __restrict__ Ap,
                                             const uint4* __restrict__ Bp,
                                             float oc[8][4]) {
    __shared__ __align__(16) unsigned short sA[2][128*40];
    __shared__ __align__(16) unsigned short sB[2][64*40];

    const int tid  = threadIdx.x;
    const int lane = tid & 31;
    const int wid  = tid >> 5;
    const int bx = blockIdx.x, by = blockIdx.y;

    #pragma unroll
    for (int i = 0; i < 8; i++)
        #pragma unroll
        for (int j = 0; j < 4; j++) oc[i][j] = 0.f;

    {
        uint32_t ad = smem_u32(&sA[0][0]);
        uint32_t bd = smem_u32(&sB[0][0]);
        for (int i = tid; i < 512; i += 256) {
            int r = i >> 2, j = i & 3;
            CP_ASYNC16(ad + r*80 + j*16, Ap + (size_t)(bx*128 + r)*32 + j);
        }
        {
            int r = tid >> 2, j = tid & 3;
            CP_ASYNC16(bd + r*80 + j*16, Bp + (size_t)(by*64 + r)*32 + j);
        }
        CP_COMMIT();
    }

    for (int t = 0; t < 8; t++) {
        if (t < 7) {
            int nb = (t + 1) & 1;
            uint32_t ad = smem_u32(&sA[nb][0]);
            uint32_t bd = smem_u32(&sB[nb][0]);
            for (int i = tid; i < 512; i += 256) {
                int r = i >> 2, j = i & 3;
                CP_ASYNC16(ad + r*80 + j*16, Ap + (size_t)(bx*128 + r)*32 + (t+1)*4 + j);
            }
            {
                int r = tid >> 2, j = tid & 3;
                CP_ASYNC16(bd + r*80 + j*16, Bp + (size_t)(by*64 + r)*32 + (t+1)*4 + j);
            }
            CP_COMMIT();
            CP_WAIT(1);
        } else {
            CP_WAIT(0);
        }
        __syncthreads();

        const int buf = t & 1;
        uint32_t qa[2][4];
        uint32_t abase = smem_u32(&sA[buf][0]) + (wid*16 + (lane & 15))*80 + (lane >> 4)*16;
        LDSM_X4(qa[0], abase);
        LDSM_X4(qa[1], abase + 32);
        uint32_t bbase = smem_u32(&sB[buf][0]) + (lane & 7)*80 + ((lane >> 3) & 3)*16;
        #pragma unroll
        for (int nt = 0; nt < 8; nt++) {
            uint32_t kb[4];
            LDSM_X4(kb, bbase + nt*640);
            MMA16816(oc[nt], qa[0], kb[0], kb[1]);
            MMA16816(oc[nt], qa[1], kb[2], kb[3]);
        }
        __syncthreads();
    }
}

// =============================================================================
// gemm_qkv_mma: grid (32, 12). Epilogue writes bf16 packs DIRECTLY into
// g_qt / g_ktp / g_vtp.
// =============================================================================
__global__ void __launch_bounds__(256, 2)
gemm_qkv_mma(const float* __restrict__ bq, const float* __restrict__ bk,
             const float* __restrict__ bv) {
    float oc[8][4];
    mma_mainloop(g_fs, g_ws, oc);

    const int lane = threadIdx.x & 31;
    const int wid  = threadIdx.x >> 5;
    const int g  = lane >> 2;
    const int tq = lane & 3;
    const int r0 = blockIdx.x*128 + wid*16 + g;

    #pragma unroll
    for (int nt = 0; nt < 8; nt++) {
        int Cg = blockIdx.y*64 + nt*8 + 2*tq;
        int z = Cg >> 8, cc = Cg & 255;
        int h = cc >> 5, d = cc & 31;
        const float* bias = (z == 0) ? bq : (z == 1) ? bk : bv;
        float bb0 = bias[cc], bb1 = bias[cc + 1];
        #pragma unroll
        for (int half = 0; half < 2; half++) {
            int r = r0 + half*8;
            int b = r >> 11, n = r & (NN - 1);
            size_t tt = ((size_t)b*HH + h)*NN + n;
            float v0 = oc[nt][half*2 + 0] + bb0;
            float v1 = oc[nt][half*2 + 1] + bb1;
            uint32_t packed;
            if (z == 0) {
                CVT_BF16X2(packed, v1*QKL, v0*QKL);
                ((uint32_t*)g_qt)[tt*24 + (d >> 1)] = packed;
            } else if (z == 1) {
                CVT_BF16X2(packed, v1, v0);
                ((uint32_t*)g_ktp)[tt*24 + (d >> 1)] = packed;
            } else {
                CVT_BF16X2(packed, v1, v0);
                ((uint32_t*)g_vtp)[tt*20 + (d >> 1)] = packed;
            }
        }
    }
}

// =============================================================================
// gemm_o_mma: grid (32, 4)
// =============================================================================
__global__ void __launch_bounds__(256, 2)
gemm_o_mma(const float* __restrict__ bo) {
    float oc[8][4];
    mma_mainloop(g_os, g_wos, oc);

    const int lane = threadIdx.x & 31;
    const int wid  = threadIdx.x >> 5;
    const int g  = lane >> 2;
    const int tq = lane & 3;
    const int r0 = blockIdx.x*128 + wid*16 + g;

    #pragma unroll
    for (int nt = 0; nt < 8; nt++) {
        int Cg = blockIdx.y*64 + nt*8 + 2*tq;
        float bb0 = bo[Cg], bb1 = bo[Cg + 1];
        #pragma unroll
        for (int half = 0; half < 2; half++) {
            int r = r0 + half*8;
            *(float2*)(g_o + (size_t)r*CC + Cg) = make_float2(
                oc[nt][half*2 + 0] + bb0, oc[nt][half*2 + 1] + bb1);
        }
    }
}

// =============================================================================
// attn_mma: flash attention, m16n8k16 bf16, 1-term logits — round-12 passing,
// epilogue writes single bf16 row into g_os.
// =============================================================================
#define KROWB 112
#define VROW 40

__global__ void __launch_bounds__(256, 2)
attn_mma() {
    __shared__ __align__(16) unsigned char sK[2][64*KROWB];
    __shared__ __align__(16) unsigned short sV[2][64*VROW];

    const int tid  = threadIdx.x;
    const int lane = tid & 31;
    const int wid  = tid >> 5;
    const int bh = blockIdx.y;
    const int qt = blockIdx.x;
    const int b = bh >> 3, h = bh & 7;

    {
        const uint4* src = g_qt + ((size_t)bh*NN + qt*128) * 6;
        for (int i = tid; i < 768; i += 256) {
            int r = i / 6, j = i - r*6;
            *(uint4*)(&sK[0][0] + r*KROWB + j*16) = src[i];
        }
    }
    __syncthreads();

    uint32_t qa[3][4];
    {
        uint32_t qbase = smem_u32(&sK[0][0]) + (wid*16 + (lane & 15))*KROWB + (lane >> 4)*16;
        #pragma unroll
        for (int c = 0; c < 3; c++) LDSM_X4(qa[c], qbase + c*32);
    }
    __syncthreads();

    float oc[4][4];
    #pragma unroll
    for (int i = 0; i < 4; i++)
        #pragma unroll
        for (int j = 0; j < 4; j++) oc[i][j] = 0.f;
    float ls0 = 0.f, ls1 = 0.f;

    const uint4* kg_src = g_ktp + (size_t)bh*NN*6;
    const uint4* vg_src = g_vtp + (size_t)bh*NN*5;

    {
        uint32_t kd = smem_u32(&sK[0][0]);
        uint32_t vd = smem_u32(&sV[0][0]);
        for (int i = tid; i < 384; i += 256) {
            int r = i / 6, j = i - r*6;
            CP_ASYNC16(kd + r*KROWB + j*16, kg_src + i);
        }
        for (int i = tid; i < 320; i += 256) CP_ASYNC16(vd + i*16, vg_src + i);
        CP_COMMIT();
    }

    for (int t = 0; t < 32; t++) {
        if (t < 31) {
            int nb = (t + 1) & 1;
            uint32_t kd = smem_u32(&sK[nb][0]);
            uint32_t vd = smem_u32(&sV[nb][0]);
            const uint4* ks = kg_src + (size_t)(t+1)*64*6;
            const uint4* vs = vg_src + (size_t)(t+1)*64*5;
            for (int i = tid; i < 384; i += 256) {
                int r = i / 6, j = i - r*6;
                CP_ASYNC16(kd + r*KROWB + j*16, ks + i);
            }
            for (int i = tid; i < 320; i += 256) CP_ASYNC16(vd + i*16, vs + i);
            CP_COMMIT();
            CP_WAIT(1);
        } else {
            CP_WAIT(0);
        }
        __syncthreads();

        const int buf = t & 1;
        uint32_t kbase = smem_u32(&sK[buf][0]);
        uint32_t vbase = smem_u32(&sV[buf][0]);

        float sc[8][4];
        #pragma unroll
        for (int kg = 0; kg < 8; kg++) {
            #pragma unroll
            for (int j = 0; j < 4; j++) sc[kg][j] = 0.f;
            uint32_t kb[6];
            uint32_t krow = kbase + (kg*8 + (lane & 7))*KROWB;
            LDSM_X4(&kb[0], krow + ((lane >> 3) & 3)*16);
            LDSM_X2(&kb[4], krow + 64 + ((lane >> 3) & 1)*16);
            #pragma unroll
            for (int c = 0; c < 3; c++)
                MMA16816(sc[kg], qa[c], kb[2*c], kb[2*c+1]);
        }

        uint32_t pa[4][4];
        #pragma unroll
        for (int pc = 0; pc < 4; pc++) {
            float e[8];
            #pragma unroll
            for (int half = 0; half < 2; half++) {
                const float* s = sc[2*pc + half];
                #pragma unroll
                for (int j = 0; j < 4; j++)
                    asm("ex2.approx.f32 %0, %1;" : "=f"(e[half*4 + j]) : "f"(s[j]));
            }
            ls0 += (e[0] + e[1]) + (e[4] + e[5]);
            ls1 += (e[2] + e[3]) + (e[6] + e[7]);
            CVT_BF16X2(pa[pc][0], e[1], e[0]);
            CVT_BF16X2(pa[pc][1], e[3], e[2]);
            CVT_BF16X2(pa[pc][2], e[5], e[4]);
            CVT_BF16X2(pa[pc][3], e[7], e[6]);
        }

        #pragma unroll
        for (int hp = 0; hp < 2; hp++) {
            #pragma unroll
            for (int pc = 0; pc < 4; pc++) {
                uint32_t vb[4];
                uint32_t va = vbase + (pc*16 + (lane & 15))*80 + hp*32 + (lane >> 4)*16;
                LDSM_X4T(vb, va);
                MMA16816(oc[2*hp],     pa[pc], vb[0], vb[1]);
                MMA16816(oc[2*hp + 1], pa[pc], vb[2], vb[3]);
            }
        }
        __syncthreads();
    }

    ls0 += __shfl_xor_sync(0xFFFFFFFFu, ls0, 1);
    ls0 += __shfl_xor_sync(0xFFFFFFFFu, ls0, 2);
    ls1 += __shfl_xor_sync(0xFFFFFFFFu, ls1, 1);
    ls1 += __shfl_xor_sync(0xFFFFFFFFu, ls1, 2);
    float inv0 = 1.f / ls0;
    float inv1 = 1.f / ls1;

    const int g  = lane >> 2;
    const int tq = lane & 3;
    const int row0 = qt*128 + wid*16 + g;
    uint32_t* orow0 = (uint32_t*)g_os + (size_t)(b*NN + row0)*128;
    uint32_t* orow1 = (uint32_t*)g_os + (size_t)(b*NN + row0 + 8)*128;
    #pragma unroll
    for (int n = 0; n < 4; n++) {
        int idx = h*16 + n*4 + tq;
        uint32_t uh;
        CVT_BF16X2(uh, oc[n][1]*inv0, oc[n][0]*inv0);
        orow0[idx] = uh;
        CVT_BF16X2(uh, oc[n][3]*inv1, oc[n][2]*inv1);
        orow1[idx] = uh;
    }
}

// =============================================================================
// Residual + LayerNorm — one warp per row, shuffle reductions
// =============================================================================
__global__ void __launch_bounds__(256)
ln_kernel(const float* __restrict__ feat,
          const float* __restrict__ ln_g, const float* __restrict__ ln_b,
          float* __restrict__ out) {
    const int lane = threadIdx.x & 31;
    const int wid  = threadIdx.x >> 5;
    const int m = blockIdx.x*8 + wid;

    const float4* f4 = (const float4*)(feat + (size_t)m*CC) + lane*2;
    const float4* o4 = (const float4*)(g_o + (size_t)m*CC) + lane*2;
    float4 a0 = f4[0], a1 = f4[1];
    float4 b0 = o4[0], b1 = o4[1];
    float v[8] = {a0.x+b0.x, a0.y+b0.y, a0.z+b0.z, a0.w+b0.w,
                  a1.x+b1.x, a1.y+b1.y, a1.z+b1.z, a1.w+b1.w};

    float s = 0.f, s2 = 0.f;
    #pragma unroll
    for (int u = 0; u < 8; u++) { s += v[u]; s2 += v[u]*v[u]; }
    #pragma unroll
    for (int d = 16; d > 0; d >>= 1) {
        s  += __shfl_xor_sync(0xFFFFFFFFu, s,  d);
        s2 += __shfl_xor_sync(0xFFFFFFFFu, s2, d);
    }
    float mu  = s * (1.f/256.f);
    float var = s2 * (1.f/256.f) - mu*mu;
    float r = rsqrtf(var + 1e-5f);

    const float4* g4 = (const float4*)ln_g + lane*2;
    const float4* bb4 = (const float4*)ln_b + lane*2;
    float4 g0 = g4[0], g1 = g4[1];
    float4 c0 = bb4[0], c1 = bb4[1];
    float gg[8] = {g0.x,g0.y,g0.z,g0.w,g1.x,g1.y,g1.z,g1.w};
    float cc[8] = {c0.x,c0.y,c0.z,c0.w,c1.x,c1.y,c1.z,c1.w};

    float4 o0, o1;
    o0.x = (v[0]-mu)*r*gg[0] + cc[0];
    o0.y = (v[1]-mu)*r*gg[1] + cc[1];
    o0.z = (v[2]-mu)*r*gg[2] + cc[2];
    o0.w = (v[3]-mu)*r*gg[3] + cc[3];
    o1.x = (v[4]-mu)*r*gg[4] + cc[4];
    o1.y = (v[5]-mu)*r*gg[5] + cc[5];
    o1.z = (v[6]-mu)*r*gg[6] + cc[6];
    o1.w = (v[7]-mu)*r*gg[7] + cc[7];
    float4* dst = (float4*)(out + (size_t)m*CC) + lane*2;
    dst[0] = o0;
    dst[1] = o1;
}

// =============================================================================
extern "C" void kernel_launch(void* const* d_in, const int* in_sizes, int n_in,
                              void* d_out, int out_size) {
    const float* feature = (const float*)d_in[0];
    const float* points  = (const float*)d_in[1];
    const float* Wq = (const float*)d_in[2];
    const float* bq = (const float*)d_in[3];
    const float* Wk = (const float*)d_in[4];
    const float* bk = (const float*)d_in[5];
    const float* Wv = (const float*)d_in[6];
    const float* bv = (const float*)d_in[7];
    const float* Wo = (const float*)d_in[8];
    const float* bo = (const float*)d_in[9];
    const float* ln_g = (const float*)d_in[10];
    const float* ln_b = (const float*)d_in[11];
    float* out = (float*)d_out;

    pack_inputs<<<768, 256>>>(feature, Wq, Wk, Wv, Wo, points);

    dim3 gq(32, 12);
    gemm_qkv_mma<<<gq, 256>>>(bq, bk, bv);

    dim3 ga(16, 16);
    attn_mma<<<ga, 256>>>();

    dim3 go(32, 4);
    gemm_o_mma<<<go, 256>>>(bo);

    ln_kernel<<<512, 256>>>(feature, ln_g, ln_b, out);
}

// round 16
// speedup vs baseline: 1.9246x; 1.1096x over previous
#include <cuda_runtime.h>
#include <cuda_bf16.h>
#include <cstdint>

#define BB 2
#define NN 2048
#define CC 256
#define HH 8
#define HD 32
#define M_TOT (BB*NN)
#define QK_SCALE 0.17677669529663687f
#define LOG2E 1.4426950408889634f
#define QKL (QK_SCALE * LOG2E)

typedef unsigned long long u64;

// ---------------- scratch (static device memory) -----------------------------
__device__ float g_o[(size_t)M_TOT*CC];
// attention packed operands (1-term bf16: 48 bf16 = 6 uint4 per Q/K row)
__device__ uint4 g_qt[(size_t)16*NN*6];    // [bh][n][48] = [qhi(36)|0(12)] *QK_SCALE*LOG2E
__device__ uint4 g_ktp[(size_t)16*NN*6];   // [bh][n][48] = [khi(36)|0(12)]
__device__ uint4 g_vtp[(size_t)16*NN*5];   // [bh][n][40] = [v(32)|0(8)]
// projection-GEMM operands (pure bf16, 256 bf16 = 32 uint4 per row)
__device__ uint4 g_fs[(size_t)M_TOT*32];   // feature rows bf16
__device__ uint4 g_os[(size_t)M_TOT*32];   // attention-out rows bf16 (written by attn)
__device__ uint4 g_ws[(size_t)768*32];     // fused Wq|Wk|Wv cols bf16
__device__ uint4 g_wos[(size_t)256*32];    // Wo cols bf16

// ---------------- helpers -----------------------------------------------------
__device__ __forceinline__ uint32_t smem_u32(const void* p) {
    uint32_t a;
    asm("{ .reg .u64 t; cvta.to.shared.u64 t, %1; cvt.u32.u64 %0, t; }" : "=r"(a) : "l"(p));
    return a;
}
#define LDSM_X4(r, a) \
    asm volatile("ldmatrix.sync.aligned.m8n8.x4.shared.b16 {%0,%1,%2,%3}, [%4];" \
        : "=r"((r)[0]), "=r"((r)[1]), "=r"((r)[2]), "=r"((r)[3]) : "r"(a))
#define LDSM_X2(r, a) \
    asm volatile("ldmatrix.sync.aligned.m8n8.x2.shared.b16 {%0,%1}, [%2];" \
        : "=r"((r)[0]), "=r"((r)[1]) : "r"(a))
#define LDSM_X4T(r, a) \
    asm volatile("ldmatrix.sync.aligned.m8n8.x4.trans.shared.b16 {%0,%1,%2,%3}, [%4];" \
        : "=r"((r)[0]), "=r"((r)[1]), "=r"((r)[2]), "=r"((r)[3]) : "r"(a))
#define MMA16816(d, a, b0, b1) \
    asm volatile("mma.sync.aligned.m16n8k16.row.col.f32.bf16.bf16.f32 " \
        "{%0,%1,%2,%3}, {%4,%5,%6,%7}, {%8,%9}, {%0,%1,%2,%3};" \
        : "+f"((d)[0]), "+f"((d)[1]), "+f"((d)[2]), "+f"((d)[3]) \
        : "r"((a)[0]), "r"((a)[1]), "r"((a)[2]), "r"((a)[3]), "r"(b0), "r"(b1))
#define CP_ASYNC16(dst_u32, src) \
    asm volatile("cp.async.cg.shared.global [%0], [%1], 16;" :: "r"(dst_u32), "l"(src))
#define CP_COMMIT() asm volatile("cp.async.commit_group;" ::: "memory")
#define CP_WAIT(n)  asm volatile("cp.async.wait_group %0;" :: "n"(n) : "memory")
#define CVT_BF16X2(d, hi, lo) \
    asm("cvt.rn.bf16x2.f32 %0, %1, %2;" : "=r"(d) : "f"(hi), "f"(lo))

__device__ __forceinline__ unsigned short bf16_hi(float v) {
    __nv_bfloat16 h = __float2bfloat16(v);
    return *(unsigned short*)&h;
}

// =============================================================================
// pack_inputs — unchanged from round 15 (passing)
// =============================================================================
__global__ void __launch_bounds__(256)
pack_inputs(const float* __restrict__ feat,
            const float* __restrict__ Wq, const float* __restrict__ Wk,
            const float* __restrict__ Wv, const float* __restrict__ Wo,
            const float* __restrict__ pts) {
    int t = blockIdx.x * 256 + threadIdx.x;
    if (t < 131072) {
        int row = t >> 5, cg = t & 31;
        const float* src = feat + (size_t)row*CC + cg*8;
        float4 f0 = *(const float4*)src;
        float4 f1 = *(const float4*)(src + 4);
        uint4 wh;
        CVT_BF16X2(wh.x, f0.y, f0.x);
        CVT_BF16X2(wh.y, f0.w, f0.z);
        CVT_BF16X2(wh.z, f1.y, f1.x);
        CVT_BF16X2(wh.w, f1.w, f1.z);
        g_fs[(size_t)row*32 + cg] = wh;
    } else if (t < 163840) {
        int t2 = t - 131072;
        int row = t2 >> 5, cg = t2 & 31;
        int z = row >> 8, cc = row & 255;
        const float* W = (z == 0) ? Wq : (z == 1) ? Wk : (z == 2) ? Wv : Wo;
        float v[8];
        #pragma unroll
        for (int u = 0; u < 8; u++) v[u] = W[(size_t)(cg*8 + u)*CC + cc];
        uint4 wh;
        CVT_BF16X2(wh.x, v[1], v[0]);
        CVT_BF16X2(wh.y, v[3], v[2]);
        CVT_BF16X2(wh.z, v[5], v[4]);
        CVT_BF16X2(wh.w, v[7], v[6]);
        uint4* dst = (z < 3) ? (g_ws + (size_t)row*32) : (g_wos + (size_t)(row - 768)*32);
        dst[cg] = wh;
    } else {
        int t3 = t - 163840;
        int bh = t3 >> 11, n = t3 & (NN-1);
        int b = bh >> 3;
        int m = b*NN + n;
        float px = pts[m*3+0], py = pts[m*3+1], pz = pts[m*3+2];
        float p2 = px*px + py*py + pz*pz;
        uint4 zr = make_uint4(0,0,0,0);
        uint4 wq, wk;
        wq.x = (uint32_t)bf16_hi(2.f*px*LOG2E) | ((uint32_t)bf16_hi(2.f*py*LOG2E) << 16);
        wq.y = (uint32_t)bf16_hi(2.f*pz*LOG2E) | ((uint32_t)bf16_hi(LOG2E) << 16);
        wq.z = 0; wq.w = 0;
        wk.x = (uint32_t)bf16_hi(px) | ((uint32_t)bf16_hi(py) << 16);
        wk.y = (uint32_t)bf16_hi(pz) | ((uint32_t)bf16_hi(-p2) << 16);
        wk.z = 0; wk.w = 0;
        g_qt[(size_t)t3*6 + 4]  = wq;
        g_qt[(size_t)t3*6 + 5]  = zr;
        g_ktp[(size_t)t3*6 + 4] = wk;
        g_ktp[(size_t)t3*6 + 5] = zr;
        g_vtp[(size_t)t3*5 + 4] = zr;
    }
}

// =============================================================================
// mma_mainloop: C[128 x 64] = A[128 x 256] * B[64 x 256]^T, pure bf16.
// 8 k32 iterations, 3-STAGE cp.async pipeline (lookahead 2).
// =============================================================================
__device__ __forceinline__ void mma_mainloop(const uint4* __restrict__ Ap,
                                             const uint4* __restrict__ Bp,
                                             float oc[8][4]) {
    __shared__ __align__(16) unsigned short sA[3][128*40];  // 30720 B
    __shared__ __align__(16) unsigned short sB[3][64*40];   // 15360 B

    const int tid  = threadIdx.x;
    const int lane = tid & 31;
    const int wid  = tid >> 5;
    const int bx = blockIdx.x, by = blockIdx.y;

    #pragma unroll
    for (int i = 0; i < 8; i++)
        #pragma unroll
        for (int j = 0; j < 4; j++) oc[i][j] = 0.f;

    const int ar = tid >> 2, aj = tid & 3;     // A: 512 loads (2 per thread? no: 512/256=2)
    const int br = tid >> 2, bj = tid & 3;     // B: 256 loads (1 per thread)

    // load tile kt into stage s
    #define GEMM_LOAD(kt, s) do { \
        uint32_t ad_ = smem_u32(&sA[s][0]); \
        uint32_t bd_ = smem_u32(&sB[s][0]); \
        CP_ASYNC16(ad_ + ar*80 + aj*16, Ap + (size_t)(bx*128 + ar)*32 + (kt)*4 + aj); \
        CP_ASYNC16(ad_ + (ar+64)*80 + aj*16, Ap + (size_t)(bx*128 + ar + 64)*32 + (kt)*4 + aj); \
        CP_ASYNC16(bd_ + br*80 + bj*16, Bp + (size_t)(by*64 + br)*32 + (kt)*4 + bj); \
        CP_COMMIT(); \
    } while (0)

    GEMM_LOAD(0, 0);
    GEMM_LOAD(1, 1);

    int cbuf = 0, lbuf = 2;
    for (int t = 0; t < 8; t++) {
        if (t < 7) { CP_WAIT(1); } else { CP_WAIT(0); }
        __syncthreads();
        if (t + 2 < 8) {
            GEMM_LOAD(t + 2, lbuf);
        }

        uint32_t qa[2][4];
        uint32_t abase = smem_u32(&sA[cbuf][0]) + (wid*16 + (lane & 15))*80 + (lane >> 4)*16;
        LDSM_X4(qa[0], abase);
        LDSM_X4(qa[1], abase + 32);
        uint32_t bbase = smem_u32(&sB[cbuf][0]) + (lane & 7)*80 + ((lane >> 3) & 3)*16;
        #pragma unroll
        for (int nt = 0; nt < 8; nt++) {
            uint32_t kb[4];
            LDSM_X4(kb, bbase + nt*640);
            MMA16816(oc[nt], qa[0], kb[0], kb[1]);
            MMA16816(oc[nt], qa[1], kb[2], kb[3]);
        }
        cbuf = (cbuf == 2) ? 0 : cbuf + 1;
        lbuf = (lbuf == 2) ? 0 : lbuf + 1;
    }
    #undef GEMM_LOAD
}

// =============================================================================
// gemm_qkv_mma: grid (32, 12). Epilogue writes bf16 packs into g_qt/g_ktp/g_vtp.
// =============================================================================
__global__ void __launch_bounds__(256, 2)
gemm_qkv_mma(const float* __restrict__ bq, const float* __restrict__ bk,
             const float* __restrict__ bv) {
    float oc[8][4];
    mma_mainloop(g_fs, g_ws, oc);

    const int lane = threadIdx.x & 31;
    const int wid  = threadIdx.x >> 5;
    const int g  = lane >> 2;
    const int tq = lane & 3;
    const int r0 = blockIdx.x*128 + wid*16 + g;

    #pragma unroll
    for (int nt = 0; nt < 8; nt++) {
        int Cg = blockIdx.y*64 + nt*8 + 2*tq;
        int z = Cg >> 8, cc = Cg & 255;
        int h = cc >> 5, d = cc & 31;
        const float* bias = (z == 0) ? bq : (z == 1) ? bk : bv;
        float bb0 = bias[cc], bb1 = bias[cc + 1];
        #pragma unroll
        for (int half = 0; half < 2; half++) {
            int r = r0 + half*8;
            int b = r >> 11, n = r & (NN - 1);
            size_t tt = ((size_t)b*HH + h)*NN + n;
            float v0 = oc[nt][half*2 + 0] + bb0;
            float v1 = oc[nt][half*2 + 1] + bb1;
            uint32_t packed;
            if (z == 0) {
                CVT_BF16X2(packed, v1*QKL, v0*QKL);
                ((uint32_t*)g_qt)[tt*24 + (d >> 1)] = packed;
            } else if (z == 1) {
                CVT_BF16X2(packed, v1, v0);
                ((uint32_t*)g_ktp)[tt*24 + (d >> 1)] = packed;
            } else {
                CVT_BF16X2(packed, v1, v0);
                ((uint32_t*)g_vtp)[tt*20 + (d >> 1)] = packed;
            }
        }
    }
}

// =============================================================================
// gemm_o_mma: grid (32, 4)
// =============================================================================
__global__ void __launch_bounds__(256, 2)
gemm_o_mma(const float* __restrict__ bo) {
    float oc[8][4];
    mma_mainloop(g_os, g_wos, oc);

    const int lane = threadIdx.x & 31;
    const int wid  = threadIdx.x >> 5;
    const int g  = lane >> 2;
    const int tq = lane & 3;
    const int r0 = blockIdx.x*128 + wid*16 + g;

    #pragma unroll
    for (int nt = 0; nt < 8; nt++) {
        int Cg = blockIdx.y*64 + nt*8 + 2*tq;
        float bb0 = bo[Cg], bb1 = bo[Cg + 1];
        #pragma unroll
        for (int half = 0; half < 2; half++) {
            int r = r0 + half*8;
            *(float2*)(g_o + (size_t)r*CC + Cg) = make_float2(
                oc[nt][half*2 + 0] + bb0, oc[nt][half*2 + 1] + bb1);
        }
    }
}

// =============================================================================
// attn_mma: flash attention, m16n8k16 bf16, 1-term logits.
// 3-STAGE cp.async pipeline over 64-key tiles (lookahead 2), 1 barrier/tile.
// =============================================================================
#define KROWB 112
#define VROW 40

__global__ void __launch_bounds__(256, 2)
attn_mma() {
    __shared__ __align__(16) unsigned char sK[3][64*KROWB];  // 3 x 7168 B
    __shared__ __align__(16) unsigned short sV[3][64*VROW];  // 3 x 5120 B

    const int tid  = threadIdx.x;
    const int lane = tid & 31;
    const int wid  = tid >> 5;
    const int bh = blockIdx.y;
    const int qt = blockIdx.x;
    const int b = bh >> 3, h = bh & 7;

    // ---- stage Q (128 rows x 96B data, stride 112B; spans sK[0..1])
    {
        const uint4* src = g_qt + ((size_t)bh*NN + qt*128) * 6;
        for (int i = tid; i < 768; i += 256) {
            int r = i / 6, j = i - r*6;
            *(uint4*)(&sK[0][0] + r*KROWB + j*16) = src[i];
        }
    }
    __syncthreads();

    uint32_t qa[3][4];
    {
        uint32_t qbase = smem_u32(&sK[0][0]) + (wid*16 + (lane & 15))*KROWB + (lane >> 4)*16;
        #pragma unroll
        for (int c = 0; c < 3; c++) LDSM_X4(qa[c], qbase + c*32);
    }
    __syncthreads();

    float oc[4][4];
    #pragma unroll
    for (int i = 0; i < 4; i++)
        #pragma unroll
        for (int j = 0; j < 4; j++) oc[i][j] = 0.f;
    float ls0 = 0.f, ls1 = 0.f;

    const uint4* kg_src = g_ktp + (size_t)bh*NN*6;
    const uint4* vg_src = g_vtp + (size_t)bh*NN*5;

    #define ATTN_LOAD(kt, s) do { \
        uint32_t kd_ = smem_u32(&sK[s][0]); \
        uint32_t vd_ = smem_u32(&sV[s][0]); \
        const uint4* ks_ = kg_src + (size_t)(kt)*384; \
        const uint4* vs_ = vg_src + (size_t)(kt)*320; \
        for (int i = tid; i < 384; i += 256) { \
            int r_ = i / 6, j_ = i - r_*6; \
            CP_ASYNC16(kd_ + r_*KROWB + j_*16, ks_ + i); \
        } \
        for (int i = tid; i < 320; i += 256) CP_ASYNC16(vd_ + i*16, vs_ + i); \
        CP_COMMIT(); \
    } while (0)

    ATTN_LOAD(0, 0);
    ATTN_LOAD(1, 1);

    int cbuf = 0, lbuf = 2;
    for (int t = 0; t < 32; t++) {
        if (t < 31) { CP_WAIT(1); } else { CP_WAIT(0); }
        __syncthreads();
        if (t + 2 < 32) {
            ATTN_LOAD(t + 2, lbuf);
        }

        uint32_t kbase = smem_u32(&sK[cbuf][0]);
        uint32_t vbase = smem_u32(&sV[cbuf][0]);

        float sc[8][4];
        #pragma unroll
        for (int kg = 0; kg < 8; kg++) {
            #pragma unroll
            for (int j = 0; j < 4; j++) sc[kg][j] = 0.f;
            uint32_t kb[6];
            uint32_t krow = kbase + (kg*8 + (lane & 7))*KROWB;
            LDSM_X4(&kb[0], krow + ((lane >> 3) & 3)*16);
            LDSM_X2(&kb[4], krow + 64 + ((lane >> 3) & 1)*16);
            #pragma unroll
            for (int c = 0; c < 3; c++)
                MMA16816(sc[kg], qa[c], kb[2*c], kb[2*c+1]);
        }

        uint32_t pa[4][4];
        #pragma unroll
        for (int pc = 0; pc < 4; pc++) {
            float e[8];
            #pragma unroll
            for (int half = 0; half < 2; half++) {
                const float* s = sc[2*pc + half];
                #pragma unroll
                for (int j = 0; j < 4; j++)
                    asm("ex2.approx.f32 %0, %1;" : "=f"(e[half*4 + j]) : "f"(s[j]));
            }
            ls0 += (e[0] + e[1]) + (e[4] + e[5]);
            ls1 += (e[2] + e[3]) + (e[6] + e[7]);
            CVT_BF16X2(pa[pc][0], e[1], e[0]);
            CVT_BF16X2(pa[pc][1], e[3], e[2]);
            CVT_BF16X2(pa[pc][2], e[5], e[4]);
            CVT_BF16X2(pa[pc][3], e[7], e[6]);
        }

        #pragma unroll
        for (int hp = 0; hp < 2; hp++) {
            #pragma unroll
            for (int pc = 0; pc < 4; pc++) {
                uint32_t vb[4];
                uint32_t va = vbase + (pc*16 + (lane & 15))*80 + hp*32 + (lane >> 4)*16;
                LDSM_X4T(vb, va);
                MMA16816(oc[2*hp],     pa[pc], vb[0], vb[1]);
                MMA16816(oc[2*hp + 1], pa[pc], vb[2], vb[3]);
            }
        }
        cbuf = (cbuf == 2) ? 0 : cbuf + 1;
        lbuf = (lbuf == 2) ? 0 : lbuf + 1;
    }
    #undef ATTN_LOAD

    ls0 += __shfl_xor_sync(0xFFFFFFFFu, ls0, 1);
    ls0 += __shfl_xor_sync(0xFFFFFFFFu, ls0, 2);
    ls1 += __shfl_xor_sync(0xFFFFFFFFu, ls1, 1);
    ls1 += __shfl_xor_sync(0xFFFFFFFFu, ls1, 2);
    float inv0 = 1.f / ls0;
    float inv1 = 1.f / ls1;

    const int g  = lane >> 2;
    const int tq = lane & 3;
    const int row0 = qt*128 + wid*16 + g;
    uint32_t* orow0 = (uint32_t*)g_os + (size_t)(b*NN + row0)*128;
    uint32_t* orow1 = (uint32_t*)g_os + (size_t)(b*NN + row0 + 8)*128;
    #pragma unroll
    for (int n = 0; n < 4; n++) {
        int idx = h*16 + n*4 + tq;
        uint32_t uh;
        CVT_BF16X2(uh, oc[n][1]*inv0, oc[n][0]*inv0);
        orow0[idx] = uh;
        CVT_BF16X2(uh, oc[n][3]*inv1, oc[n][2]*inv1);
        orow1[idx] = uh;
    }
}

// =============================================================================
// Residual + LayerNorm — one warp per row, shuffle reductions
// =============================================================================
__global__ void __launch_bounds__(256)
ln_kernel(const float* __restrict__ feat,
          const float* __restrict__ ln_g, const float* __restrict__ ln_b,
          float* __restrict__ out) {
    const int lane = threadIdx.x & 31;
    const int wid  = threadIdx.x >> 5;
    const int m = blockIdx.x*8 + wid;

    const float4* f4 = (const float4*)(feat + (size_t)m*CC) + lane*2;
    const float4* o4 = (const float4*)(g_o + (size_t)m*CC) + lane*2;
    float4 a0 = f4[0], a1 = f4[1];
    float4 b0 = o4[0], b1 = o4[1];
    float v[8] = {a0.x+b0.x, a0.y+b0.y, a0.z+b0.z, a0.w+b0.w,
                  a1.x+b1.x, a1.y+b1.y, a1.z+b1.z, a1.w+b1.w};

    float s = 0.f, s2 = 0.f;
    #pragma unroll
    for (int u = 0; u < 8; u++) { s += v[u]; s2 += v[u]*v[u]; }
    #pragma unroll
    for (int d = 16; d > 0; d >>= 1) {
        s  += __shfl_xor_sync(0xFFFFFFFFu, s,  d);
        s2 += __shfl_xor_sync(0xFFFFFFFFu, s2, d);
    }
    float mu  = s * (1.f/256.f);
    float var = s2 * (1.f/256.f) - mu*mu;
    float r = rsqrtf(var + 1e-5f);

    const float4* g4 = (const float4*)ln_g + lane*2;
    const float4* bb4 = (const float4*)ln_b + lane*2;
    float4 g0 = g4[0], g1 = g4[1];
    float4 c0 = bb4[0], c1 = bb4[1];
    float gg[8] = {g0.x,g0.y,g0.z,g0.w,g1.x,g1.y,g1.z,g1.w};
    float cc[8] = {c0.x,c0.y,c0.z,c0.w,c1.x,c1.y,c1.z,c1.w};

    float4 o0, o1;
    o0.x = (v[0]-mu)*r*gg[0] + cc[0];
    o0.y = (v[1]-mu)*r*gg[1] + cc[1];
    o0.z = (v[2]-mu)*r*gg[2] + cc[2];
    o0.w = (v[3]-mu)*r*gg[3] + cc[3];
    o1.x = (v[4]-mu)*r*gg[4] + cc[4];
    o1.y = (v[5]-mu)*r*gg[5] + cc[5];
    o1.z = (v[6]-mu)*r*gg[6] + cc[6];
    o1.w = (v[7]-mu)*r*gg[7] + cc[7];
    float4* dst = (float4*)(out + (size_t)m*CC) + lane*2;
    dst[0] = o0;
    dst[1] = o1;
}

// =============================================================================
extern "C" void kernel_launch(void* const* d_in, const int* in_sizes, int n_in,
                              void* d_out, int out_size) {
    const float* feature = (const float*)d_in[0];
    const float* points  = (const float*)d_in[1];
    const float* Wq = (const float*)d_in[2];
    const float* bq = (const float*)d_in[3];
    const float* Wk = (const float*)d_in[4];
    const float* bk = (const float*)d_in[5];
    const float* Wv = (const float*)d_in[6];
    const float* bv = (const float*)d_in[7];
    const float* Wo = (const float*)d_in[8];
    const float* bo = (const float*)d_in[9];
    const float* ln_g = (const float*)d_in[10];
    const float* ln_b = (const float*)d_in[11];
    float* out = (float*)d_out;

    pack_inputs<<<768, 256>>>(feature, Wq, Wk, Wv, Wo, points);

    dim3 gq(32, 12);
    gemm_qkv_mma<<<gq, 256>>>(bq, bk, bv);

    dim3 ga(16, 16);
    attn_mma<<<ga, 256>>>();

    dim3 go(32, 4);
    gemm_o_mma<<<go, 256>>>(bo);

    ln_kernel<<<512, 256>>>(feature, ln_g, ln_b, out);
}